// round 1
// baseline (speedup 1.0000x reference)
#include <cuda_runtime.h>

// Problem constants
#define NCLS 64
#define NGRP 8
#define NSEQ 32
#define DIM  2048
#define OCH  256
#define NPRO 5
#define MTOT (NCLS * NGRP * NSEQ)   // 16384

// Scratch (device globals; no runtime allocation allowed)
__device__ float g_ctx[(size_t)MTOT * DIM];    // 134 MB
__device__ float g_feats[(size_t)MTOT * DIM];  // 134 MB

// ---------------------------------------------------------------------------
// Kernel A: per (class, group) inner self-attention -> ctx
//   e   = X @ W1^T            [32,256]
//   att = softmax(e e^T / 16) [32,32]
//   ctx = att @ X             [32,2048]
// One block per (c,g); 256 threads.
// ---------------------------------------------------------------------------
__global__ __launch_bounds__(256) void kA(const float* __restrict__ Xall,
                                          const float* __restrict__ w1)
{
    const int blk = blockIdx.x;  // c*8+g
    const float* X  = Xall + (size_t)blk * NSEQ * DIM;
    float* CTX      = g_ctx + (size_t)blk * NSEQ * DIM;

    __shared__ __align__(16) float Xs[32][36];    // X k-tile, transposed [k][n]
    __shared__ __align__(16) float Ws[32][260];   // w1 k-tile transposed [k][o]; reused as es[n][o] and Xc
    __shared__ __align__(16) float Ss[32][32];    // scores -> att (in place)

    const int tid = threadIdx.x;
    const int tx = tid & 31;   // o-quad index
    const int ty = tid >> 5;   // n-quad index (0..7)

    // ---- GEMM1: e[n][o] = sum_k X[n][k] * w1[o][k] ----
    float acc[4][8];
#pragma unroll
    for (int i = 0; i < 4; ++i)
#pragma unroll
        for (int j = 0; j < 8; ++j) acc[i][j] = 0.f;

    for (int k0 = 0; k0 < DIM; k0 += 32) {
        // X tile: 32 rows x 32 k (coalesced, stored transposed)
        {
            int row = tid >> 3, c4 = tid & 7;
            float4 v = *(const float4*)(X + (size_t)row * DIM + k0 + c4 * 4);
            Xs[c4 * 4 + 0][row] = v.x;
            Xs[c4 * 4 + 1][row] = v.y;
            Xs[c4 * 4 + 2][row] = v.z;
            Xs[c4 * 4 + 3][row] = v.w;
        }
        // w1 tile: 256 o x 32 k (coalesced, stored transposed)
#pragma unroll
        for (int r = 0; r < 8; ++r) {
            int idx = r * 256 + tid;
            int o = idx >> 3, c4 = idx & 7;
            float4 v = *(const float4*)(w1 + (size_t)o * DIM + k0 + c4 * 4);
            Ws[c4 * 4 + 0][o] = v.x;
            Ws[c4 * 4 + 1][o] = v.y;
            Ws[c4 * 4 + 2][o] = v.z;
            Ws[c4 * 4 + 3][o] = v.w;
        }
        __syncthreads();
#pragma unroll
        for (int k = 0; k < 32; ++k) {
            float4 av  = *(const float4*)&Xs[k][ty * 4];
            float4 bv0 = *(const float4*)&Ws[k][tx * 4];
            float4 bv1 = *(const float4*)&Ws[k][128 + tx * 4];
            float a[4] = {av.x, av.y, av.z, av.w};
            float b[8] = {bv0.x, bv0.y, bv0.z, bv0.w, bv1.x, bv1.y, bv1.z, bv1.w};
#pragma unroll
            for (int i = 0; i < 4; ++i)
#pragma unroll
                for (int j = 0; j < 8; ++j) acc[i][j] += a[i] * b[j];
        }
        __syncthreads();
    }

    // Write e into smem (reuse Ws as es[n][o], stride 260)
#pragma unroll
    for (int i = 0; i < 4; ++i) {
        *(float4*)&Ws[ty * 4 + i][tx * 4]       = make_float4(acc[i][0], acc[i][1], acc[i][2], acc[i][3]);
        *(float4*)&Ws[ty * 4 + i][128 + tx * 4] = make_float4(acc[i][4], acc[i][5], acc[i][6], acc[i][7]);
    }
    __syncthreads();

    // ---- scores S[n][m] = (1/16) * sum_o e[n][o] e[m][o] ----
    {
        int n = tid >> 3;
        int mbase = (tid & 7) * 4;
        float s0 = 0.f, s1 = 0.f, s2 = 0.f, s3 = 0.f;
        for (int o = 0; o < OCH; o += 4) {
            float4 a  = *(const float4*)&Ws[n][o];
            float4 b0 = *(const float4*)&Ws[mbase + 0][o];
            float4 b1 = *(const float4*)&Ws[mbase + 1][o];
            float4 b2 = *(const float4*)&Ws[mbase + 2][o];
            float4 b3 = *(const float4*)&Ws[mbase + 3][o];
            s0 += a.x * b0.x + a.y * b0.y + a.z * b0.z + a.w * b0.w;
            s1 += a.x * b1.x + a.y * b1.y + a.z * b1.z + a.w * b1.w;
            s2 += a.x * b2.x + a.y * b2.y + a.z * b2.z + a.w * b2.w;
            s3 += a.x * b3.x + a.y * b3.y + a.z * b3.z + a.w * b3.w;
        }
        Ss[n][mbase + 0] = s0 * 0.0625f;
        Ss[n][mbase + 1] = s1 * 0.0625f;
        Ss[n][mbase + 2] = s2 * 0.0625f;
        Ss[n][mbase + 3] = s3 * 0.0625f;
    }
    __syncthreads();

    // ---- softmax over m (rows of Ss), in place ----
    {
        int w = tid >> 5, lane = tid & 31;
#pragma unroll
        for (int rr = 0; rr < 4; ++rr) {
            int n = w * 4 + rr;
            float v = Ss[n][lane];
            float mx = v;
#pragma unroll
            for (int off = 16; off > 0; off >>= 1)
                mx = fmaxf(mx, __shfl_xor_sync(0xffffffffu, mx, off));
            float ex = expf(v - mx);
            float sm = ex;
#pragma unroll
            for (int off = 16; off > 0; off >>= 1)
                sm += __shfl_xor_sync(0xffffffffu, sm, off);
            Ss[n][lane] = ex / sm;
        }
    }
    __syncthreads();

    // ---- ctx[n][d] = sum_m att[n][m] X[m][d] ----
    // Reuse Ws region as Xc[32][68]
    float* Xc = &Ws[0][0];
    const int XCS = 68;
    const int txc = tid & 63;   // d within chunk
    const int tyc = tid >> 6;   // n-group (0..3), 8 rows each

    for (int d0 = 0; d0 < DIM; d0 += 64) {
#pragma unroll
        for (int r = 0; r < 2; ++r) {
            int idx = r * 256 + tid;
            int row = idx >> 4, c4 = idx & 15;
            float4 v = *(const float4*)(X + (size_t)row * DIM + d0 + c4 * 4);
            *(float4*)&Xc[row * XCS + c4 * 4] = v;
        }
        __syncthreads();

        float outv[8];
#pragma unroll
        for (int i = 0; i < 8; ++i) outv[i] = 0.f;

#pragma unroll
        for (int m4 = 0; m4 < 32; m4 += 4) {
            float xv0 = Xc[(m4 + 0) * XCS + txc];
            float xv1 = Xc[(m4 + 1) * XCS + txc];
            float xv2 = Xc[(m4 + 2) * XCS + txc];
            float xv3 = Xc[(m4 + 3) * XCS + txc];
#pragma unroll
            for (int i = 0; i < 8; ++i) {
                float4 a = *(const float4*)&Ss[tyc * 8 + i][m4];
                outv[i] += a.x * xv0 + a.y * xv1 + a.z * xv2 + a.w * xv3;
            }
        }
#pragma unroll
        for (int i = 0; i < 8; ++i)
            CTX[(size_t)(tyc * 8 + i) * DIM + d0 + txc] = outv[i];
        __syncthreads();
    }
}

// ---------------------------------------------------------------------------
// Kernel B: Y = ctx @ T^T  (M=16384, N=2048, K=2048), fused epilogue:
//   feats = X + relu(Y)
// 128x128x16 tiles, 256 threads, 8x8 per thread, double-buffered smem.
// ---------------------------------------------------------------------------
__global__ __launch_bounds__(256) void kB(const float* __restrict__ T,
                                          const float* __restrict__ X)
{
    __shared__ __align__(16) float As[2][16][132];
    __shared__ __align__(16) float Bs[2][16][132];

    const int tid = threadIdx.x;
    const int tx = tid & 15;    // n micro
    const int ty = tid >> 4;    // m micro
    const int m0 = blockIdx.y * 128;
    const int n0 = blockIdx.x * 128;

    const float* Ab = g_ctx + (size_t)m0 * DIM;
    const float* Bb = T + (size_t)n0 * DIM;

    const int r0 = tid >> 2;          // 0..63
    const int c0 = (tid & 3) * 4;     // 0,4,8,12

    float4 a0, a1, b0, b1;

    // preload tile 0
    a0 = *(const float4*)(Ab + (size_t)r0 * DIM + c0);
    a1 = *(const float4*)(Ab + (size_t)(r0 + 64) * DIM + c0);
    b0 = *(const float4*)(Bb + (size_t)r0 * DIM + c0);
    b1 = *(const float4*)(Bb + (size_t)(r0 + 64) * DIM + c0);

    As[0][c0 + 0][r0] = a0.x; As[0][c0 + 1][r0] = a0.y; As[0][c0 + 2][r0] = a0.z; As[0][c0 + 3][r0] = a0.w;
    As[0][c0 + 0][r0 + 64] = a1.x; As[0][c0 + 1][r0 + 64] = a1.y; As[0][c0 + 2][r0 + 64] = a1.z; As[0][c0 + 3][r0 + 64] = a1.w;
    Bs[0][c0 + 0][r0] = b0.x; Bs[0][c0 + 1][r0] = b0.y; Bs[0][c0 + 2][r0] = b0.z; Bs[0][c0 + 3][r0] = b0.w;
    Bs[0][c0 + 0][r0 + 64] = b1.x; Bs[0][c0 + 1][r0 + 64] = b1.y; Bs[0][c0 + 2][r0 + 64] = b1.z; Bs[0][c0 + 3][r0 + 64] = b1.w;
    __syncthreads();

    float acc[8][8];
#pragma unroll
    for (int i = 0; i < 8; ++i)
#pragma unroll
        for (int j = 0; j < 8; ++j) acc[i][j] = 0.f;

    const int NKT = DIM / 16;  // 128
    int buf = 0;
    for (int kt = 0; kt < NKT; ++kt) {
        const bool has = (kt + 1) < NKT;
        if (has) {
            int kn = (kt + 1) * 16;
            a0 = *(const float4*)(Ab + (size_t)r0 * DIM + kn + c0);
            a1 = *(const float4*)(Ab + (size_t)(r0 + 64) * DIM + kn + c0);
            b0 = *(const float4*)(Bb + (size_t)r0 * DIM + kn + c0);
            b1 = *(const float4*)(Bb + (size_t)(r0 + 64) * DIM + kn + c0);
        }
#pragma unroll
        for (int k = 0; k < 16; ++k) {
            float4 va0 = *(const float4*)&As[buf][k][ty * 4];
            float4 va1 = *(const float4*)&As[buf][k][64 + ty * 4];
            float4 vb0 = *(const float4*)&Bs[buf][k][tx * 4];
            float4 vb1 = *(const float4*)&Bs[buf][k][64 + tx * 4];
            float a[8] = {va0.x, va0.y, va0.z, va0.w, va1.x, va1.y, va1.z, va1.w};
            float b[8] = {vb0.x, vb0.y, vb0.z, vb0.w, vb1.x, vb1.y, vb1.z, vb1.w};
#pragma unroll
            for (int i = 0; i < 8; ++i)
#pragma unroll
                for (int j = 0; j < 8; ++j) acc[i][j] += a[i] * b[j];
        }
        if (has) {
            buf ^= 1;
            As[buf][c0 + 0][r0] = a0.x; As[buf][c0 + 1][r0] = a0.y; As[buf][c0 + 2][r0] = a0.z; As[buf][c0 + 3][r0] = a0.w;
            As[buf][c0 + 0][r0 + 64] = a1.x; As[buf][c0 + 1][r0 + 64] = a1.y; As[buf][c0 + 2][r0 + 64] = a1.z; As[buf][c0 + 3][r0 + 64] = a1.w;
            Bs[buf][c0 + 0][r0] = b0.x; Bs[buf][c0 + 1][r0] = b0.y; Bs[buf][c0 + 2][r0] = b0.z; Bs[buf][c0 + 3][r0] = b0.w;
            Bs[buf][c0 + 0][r0 + 64] = b1.x; Bs[buf][c0 + 1][r0 + 64] = b1.y; Bs[buf][c0 + 2][r0 + 64] = b1.z; Bs[buf][c0 + 3][r0 + 64] = b1.w;
            __syncthreads();
        }
    }

    // epilogue: feats = X + relu(Y)
    const float* Xb = X + (size_t)m0 * DIM + n0;
    float* Fb = g_feats + (size_t)m0 * DIM + n0;
#pragma unroll
    for (int ih = 0; ih < 2; ++ih)
#pragma unroll
        for (int i = 0; i < 4; ++i) {
            int m = ih * 64 + ty * 4 + i;
#pragma unroll
            for (int jh = 0; jh < 2; ++jh) {
                int e = jh * 64 + tx * 4;
                float4 xv = *(const float4*)(Xb + (size_t)m * DIM + e);
                float4 o;
                o.x = xv.x + fmaxf(acc[ih * 4 + i][jh * 4 + 0], 0.f);
                o.y = xv.y + fmaxf(acc[ih * 4 + i][jh * 4 + 1], 0.f);
                o.z = xv.z + fmaxf(acc[ih * 4 + i][jh * 4 + 2], 0.f);
                o.w = xv.w + fmaxf(acc[ih * 4 + i][jh * 4 + 3], 0.f);
                *(float4*)(Fb + (size_t)m * DIM + e) = o;
            }
        }
}

// ---------------------------------------------------------------------------
// Kernel C: inter cross-attention, per class (64 blocks, 256 threads).
// Uses the folded form: q = (protos @ w2^T) @ w1   [5,2048]
//   s[n][p] = feats[n,:] . q[p,:]   -> softmax over n -> out = att2 @ feats
// ---------------------------------------------------------------------------
__global__ __launch_bounds__(256) void kC(const float* __restrict__ protos,
                                          const float* __restrict__ w1i,
                                          const float* __restrict__ w2i,
                                          float* __restrict__ outp)
{
    const int c = blockIdx.x;
    __shared__ __align__(16) float qs[NPRO * DIM];   // protos, then q
    __shared__ __align__(16) float ps[NPRO * OCH];   // p_e, then s/att2

    const int tid = threadIdx.x;
    const int lane = tid & 31;
    const int w = tid >> 5;
    const float* F = g_feats + (size_t)c * (NGRP * NSEQ) * DIM;  // [256][2048]

    // load protos[c] into smem
    {
        const float4* src = (const float4*)(protos + (size_t)c * NPRO * DIM);
        float4* dst = (float4*)qs;
        for (int i = tid; i < NPRO * DIM / 4; i += 256) dst[i] = src[i];
    }
    __syncthreads();

    // p_e[p][o] = sum_d protos[p][d] * w2[o][d]
    for (int o = w; o < OCH; o += 8) {
        float acc[NPRO] = {0.f, 0.f, 0.f, 0.f, 0.f};
        for (int d = lane; d < DIM; d += 32) {
            float wv = w2i[(size_t)o * DIM + d];
#pragma unroll
            for (int p = 0; p < NPRO; ++p) acc[p] += qs[p * DIM + d] * wv;
        }
#pragma unroll
        for (int p = 0; p < NPRO; ++p) {
#pragma unroll
            for (int off = 16; off > 0; off >>= 1)
                acc[p] += __shfl_xor_sync(0xffffffffu, acc[p], off);
        }
        if (lane == 0) {
#pragma unroll
            for (int p = 0; p < NPRO; ++p) ps[p * OCH + o] = acc[p];
        }
    }
    __syncthreads();

    // q[p][d] = sum_o p_e[p][o] * w1[o][d]   (overwrite qs)
    for (int d = tid; d < DIM; d += 256) {
        float acc[NPRO] = {0.f, 0.f, 0.f, 0.f, 0.f};
        for (int o = 0; o < OCH; ++o) {
            float wv = w1i[(size_t)o * DIM + d];
#pragma unroll
            for (int p = 0; p < NPRO; ++p) acc[p] += ps[p * OCH + o] * wv;
        }
#pragma unroll
        for (int p = 0; p < NPRO; ++p) qs[p * DIM + d] = acc[p];
    }
    __syncthreads();

    // s[n][p] = (1/16) feats[n,:] . q[p,:]  (into ps)
    for (int n = w; n < 256; n += 8) {
        float acc[NPRO] = {0.f, 0.f, 0.f, 0.f, 0.f};
        const float* fr = F + (size_t)n * DIM;
        for (int d = lane; d < DIM; d += 32) {
            float fv = fr[d];
#pragma unroll
            for (int p = 0; p < NPRO; ++p) acc[p] += fv * qs[p * DIM + d];
        }
#pragma unroll
        for (int p = 0; p < NPRO; ++p) {
#pragma unroll
            for (int off = 16; off > 0; off >>= 1)
                acc[p] += __shfl_xor_sync(0xffffffffu, acc[p], off);
        }
        if (lane == 0) {
#pragma unroll
            for (int p = 0; p < NPRO; ++p) ps[p * OCH + n] = acc[p] * 0.0625f;
        }
    }
    __syncthreads();

    // softmax over n per prototype (warps 0..4)
    if (w < NPRO) {
        const int p = w;
        float mx = -1e30f;
        for (int n = lane; n < 256; n += 32) mx = fmaxf(mx, ps[p * OCH + n]);
#pragma unroll
        for (int off = 16; off > 0; off >>= 1)
            mx = fmaxf(mx, __shfl_xor_sync(0xffffffffu, mx, off));
        float sm = 0.f;
        for (int n = lane; n < 256; n += 32) {
            float e = expf(ps[p * OCH + n] - mx);
            ps[p * OCH + n] = e;
            sm += e;
        }
#pragma unroll
        for (int off = 16; off > 0; off >>= 1)
            sm += __shfl_xor_sync(0xffffffffu, sm, off);
        float inv = 1.f / sm;
        for (int n = lane; n < 256; n += 32) ps[p * OCH + n] *= inv;
    }
    __syncthreads();

    // out[p][d] = sum_n att2[p][n] * feats[n][d]
    float* ob = outp + (size_t)c * NPRO * DIM;
    for (int d = tid; d < DIM; d += 256) {
        float acc[NPRO] = {0.f, 0.f, 0.f, 0.f, 0.f};
        for (int n = 0; n < 256; ++n) {
            float fv = F[(size_t)n * DIM + d];
#pragma unroll
            for (int p = 0; p < NPRO; ++p) acc[p] += ps[p * OCH + n] * fv;
        }
#pragma unroll
        for (int p = 0; p < NPRO; ++p) ob[(size_t)p * DIM + d] = acc[p];
    }
}

// ---------------------------------------------------------------------------
extern "C" void kernel_launch(void* const* d_in, const int* in_sizes, int n_in,
                              void* d_out, int out_size)
{
    const float* topk   = (const float*)d_in[0];  // [64,8,32,2048]
    const float* protos = (const float*)d_in[1];  // [64,5,2048]
    const float* w1     = (const float*)d_in[2];  // [256,2048]
    const float* trans  = (const float*)d_in[3];  // [2048,2048]
    const float* w1i    = (const float*)d_in[4];  // [256,2048]
    const float* w2i    = (const float*)d_in[5];  // [256,2048]
    float* out = (float*)d_out;

    kA<<<NCLS * NGRP, 256>>>(topk, w1);
    dim3 gB(DIM / 128, MTOT / 128);  // (16, 128)
    kB<<<gB, 256>>>(trans, topk);
    kC<<<NCLS, 256>>>(protos, w1i, w2i, out);
}

// round 3
// speedup vs baseline: 1.5701x; 1.5701x over previous
#include <cuda_runtime.h>
#include <cstdint>

// Problem constants
#define NCLS 64
#define NGRP 8
#define NSEQ 32
#define DIM  2048
#define OCH  256
#define NPRO 5
#define MTOT (NCLS * NGRP * NSEQ)   // 16384

// Scratch (device globals; no runtime allocation allowed)
__device__ float g_ctx[(size_t)MTOT * DIM];    // 134 MB
__device__ float g_feats[(size_t)MTOT * DIM];  // 134 MB

__device__ __forceinline__ float to_tf32(float x) {
    unsigned int t;
    asm("cvt.rna.tf32.f32 %0, %1;" : "=r"(t) : "f"(x));
    return __uint_as_float(t);
}

// ---------------------------------------------------------------------------
// Kernel A: per (class, group) inner self-attention -> ctx   (unchanged)
// ---------------------------------------------------------------------------
__global__ __launch_bounds__(256) void kA(const float* __restrict__ Xall,
                                          const float* __restrict__ w1)
{
    const int blk = blockIdx.x;  // c*8+g
    const float* X  = Xall + (size_t)blk * NSEQ * DIM;
    float* CTX      = g_ctx + (size_t)blk * NSEQ * DIM;

    __shared__ __align__(16) float Xs[32][36];
    __shared__ __align__(16) float Ws[32][260];
    __shared__ __align__(16) float Ss[32][32];

    const int tid = threadIdx.x;
    const int tx = tid & 31;
    const int ty = tid >> 5;

    float acc[4][8];
#pragma unroll
    for (int i = 0; i < 4; ++i)
#pragma unroll
        for (int j = 0; j < 8; ++j) acc[i][j] = 0.f;

    for (int k0 = 0; k0 < DIM; k0 += 32) {
        {
            int row = tid >> 3, c4 = tid & 7;
            float4 v = *(const float4*)(X + (size_t)row * DIM + k0 + c4 * 4);
            Xs[c4 * 4 + 0][row] = v.x;
            Xs[c4 * 4 + 1][row] = v.y;
            Xs[c4 * 4 + 2][row] = v.z;
            Xs[c4 * 4 + 3][row] = v.w;
        }
#pragma unroll
        for (int r = 0; r < 8; ++r) {
            int idx = r * 256 + tid;
            int o = idx >> 3, c4 = idx & 7;
            float4 v = *(const float4*)(w1 + (size_t)o * DIM + k0 + c4 * 4);
            Ws[c4 * 4 + 0][o] = v.x;
            Ws[c4 * 4 + 1][o] = v.y;
            Ws[c4 * 4 + 2][o] = v.z;
            Ws[c4 * 4 + 3][o] = v.w;
        }
        __syncthreads();
#pragma unroll
        for (int k = 0; k < 32; ++k) {
            float4 av  = *(const float4*)&Xs[k][ty * 4];
            float4 bv0 = *(const float4*)&Ws[k][tx * 4];
            float4 bv1 = *(const float4*)&Ws[k][128 + tx * 4];
            float a[4] = {av.x, av.y, av.z, av.w};
            float b[8] = {bv0.x, bv0.y, bv0.z, bv0.w, bv1.x, bv1.y, bv1.z, bv1.w};
#pragma unroll
            for (int i = 0; i < 4; ++i)
#pragma unroll
                for (int j = 0; j < 8; ++j) acc[i][j] += a[i] * b[j];
        }
        __syncthreads();
    }

#pragma unroll
    for (int i = 0; i < 4; ++i) {
        *(float4*)&Ws[ty * 4 + i][tx * 4]       = make_float4(acc[i][0], acc[i][1], acc[i][2], acc[i][3]);
        *(float4*)&Ws[ty * 4 + i][128 + tx * 4] = make_float4(acc[i][4], acc[i][5], acc[i][6], acc[i][7]);
    }
    __syncthreads();

    {
        int n = tid >> 3;
        int mbase = (tid & 7) * 4;
        float s0 = 0.f, s1 = 0.f, s2 = 0.f, s3 = 0.f;
        for (int o = 0; o < OCH; o += 4) {
            float4 a  = *(const float4*)&Ws[n][o];
            float4 b0 = *(const float4*)&Ws[mbase + 0][o];
            float4 b1 = *(const float4*)&Ws[mbase + 1][o];
            float4 b2 = *(const float4*)&Ws[mbase + 2][o];
            float4 b3 = *(const float4*)&Ws[mbase + 3][o];
            s0 += a.x * b0.x + a.y * b0.y + a.z * b0.z + a.w * b0.w;
            s1 += a.x * b1.x + a.y * b1.y + a.z * b1.z + a.w * b1.w;
            s2 += a.x * b2.x + a.y * b2.y + a.z * b2.z + a.w * b2.w;
            s3 += a.x * b3.x + a.y * b3.y + a.z * b3.z + a.w * b3.w;
        }
        Ss[n][mbase + 0] = s0 * 0.0625f;
        Ss[n][mbase + 1] = s1 * 0.0625f;
        Ss[n][mbase + 2] = s2 * 0.0625f;
        Ss[n][mbase + 3] = s3 * 0.0625f;
    }
    __syncthreads();

    {
        int w = tid >> 5, lane = tid & 31;
#pragma unroll
        for (int rr = 0; rr < 4; ++rr) {
            int n = w * 4 + rr;
            float v = Ss[n][lane];
            float mx = v;
#pragma unroll
            for (int off = 16; off > 0; off >>= 1)
                mx = fmaxf(mx, __shfl_xor_sync(0xffffffffu, mx, off));
            float ex = expf(v - mx);
            float sm = ex;
#pragma unroll
            for (int off = 16; off > 0; off >>= 1)
                sm += __shfl_xor_sync(0xffffffffu, sm, off);
            Ss[n][lane] = ex / sm;
        }
    }
    __syncthreads();

    float* Xc = &Ws[0][0];
    const int XCS = 68;
    const int txc = tid & 63;
    const int tyc = tid >> 6;

    for (int d0 = 0; d0 < DIM; d0 += 64) {
#pragma unroll
        for (int r = 0; r < 2; ++r) {
            int idx = r * 256 + tid;
            int row = idx >> 4, c4 = idx & 15;
            float4 v = *(const float4*)(X + (size_t)row * DIM + d0 + c4 * 4);
            *(float4*)&Xc[row * XCS + c4 * 4] = v;
        }
        __syncthreads();

        float outv[8];
#pragma unroll
        for (int i = 0; i < 8; ++i) outv[i] = 0.f;

#pragma unroll
        for (int m4 = 0; m4 < 32; m4 += 4) {
            float xv0 = Xc[(m4 + 0) * XCS + txc];
            float xv1 = Xc[(m4 + 1) * XCS + txc];
            float xv2 = Xc[(m4 + 2) * XCS + txc];
            float xv3 = Xc[(m4 + 3) * XCS + txc];
#pragma unroll
            for (int i = 0; i < 8; ++i) {
                float4 a = *(const float4*)&Ss[tyc * 8 + i][m4];
                outv[i] += a.x * xv0 + a.y * xv1 + a.z * xv2 + a.w * xv3;
            }
        }
#pragma unroll
        for (int i = 0; i < 8; ++i)
            CTX[(size_t)(tyc * 8 + i) * DIM + d0 + txc] = outv[i];
        __syncthreads();
    }
}

// ---------------------------------------------------------------------------
// Kernel B (tf32 tensor cores): Y = ctx @ T^T, feats = X + relu(Y)
// M=16384, N=2048, K=2048. 128x128x16 tiles, 8 warps, warp tile 64x32
// via m16n8k8 tf32 mma.sync. Smem K-major, stride 136 (conflict-free frags).
// ---------------------------------------------------------------------------
__global__ __launch_bounds__(256) void kB(const float* __restrict__ T,
                                          const float* __restrict__ X)
{
    __shared__ __align__(16) float As[2][16][136];
    __shared__ __align__(16) float Bs[2][16][136];

    const int tid  = threadIdx.x;
    const int lane = tid & 31;
    const int wid  = tid >> 5;
    const int wm   = (wid & 1) * 64;   // warp m offset within block
    const int wn   = (wid >> 1) * 32;  // warp n offset within block

    const int m0 = blockIdx.y * 128;
    const int n0 = blockIdx.x * 128;

    const float* Ab = g_ctx + (size_t)m0 * DIM;
    const float* Bb = T + (size_t)n0 * DIM;

    // loader: each thread loads 2 float4 from A and 2 from B per k-tile
    const int r0 = tid >> 2;        // 0..63
    const int c0 = (tid & 3) * 4;   // 0,4,8,12

    float4 a0, a1, b0, b1;

    a0 = *(const float4*)(Ab + (size_t)r0 * DIM + c0);
    a1 = *(const float4*)(Ab + (size_t)(r0 + 64) * DIM + c0);
    b0 = *(const float4*)(Bb + (size_t)r0 * DIM + c0);
    b1 = *(const float4*)(Bb + (size_t)(r0 + 64) * DIM + c0);

#define STASH(buf_) do {                                                        \
    As[buf_][c0 + 0][r0] = to_tf32(a0.x); As[buf_][c0 + 1][r0] = to_tf32(a0.y); \
    As[buf_][c0 + 2][r0] = to_tf32(a0.z); As[buf_][c0 + 3][r0] = to_tf32(a0.w); \
    As[buf_][c0 + 0][r0 + 64] = to_tf32(a1.x); As[buf_][c0 + 1][r0 + 64] = to_tf32(a1.y); \
    As[buf_][c0 + 2][r0 + 64] = to_tf32(a1.z); As[buf_][c0 + 3][r0 + 64] = to_tf32(a1.w); \
    Bs[buf_][c0 + 0][r0] = to_tf32(b0.x); Bs[buf_][c0 + 1][r0] = to_tf32(b0.y); \
    Bs[buf_][c0 + 2][r0] = to_tf32(b0.z); Bs[buf_][c0 + 3][r0] = to_tf32(b0.w); \
    Bs[buf_][c0 + 0][r0 + 64] = to_tf32(b1.x); Bs[buf_][c0 + 1][r0 + 64] = to_tf32(b1.y); \
    Bs[buf_][c0 + 2][r0 + 64] = to_tf32(b1.z); Bs[buf_][c0 + 3][r0 + 64] = to_tf32(b1.w); \
} while (0)

    STASH(0);
    __syncthreads();

    float acc[4][4][4];
#pragma unroll
    for (int mi = 0; mi < 4; ++mi)
#pragma unroll
        for (int ni = 0; ni < 4; ++ni)
#pragma unroll
            for (int r = 0; r < 4; ++r) acc[mi][ni][r] = 0.f;

    const int arow = lane >> 2;   // 0..7
    const int akr  = lane & 3;    // 0..3

    const int NKT = DIM / 16;  // 128
    int buf = 0;
    for (int kt = 0; kt < NKT; ++kt) {
        const bool has = (kt + 1) < NKT;
        if (has) {
            int kn = (kt + 1) * 16;
            a0 = *(const float4*)(Ab + (size_t)r0 * DIM + kn + c0);
            a1 = *(const float4*)(Ab + (size_t)(r0 + 64) * DIM + kn + c0);
            b0 = *(const float4*)(Bb + (size_t)r0 * DIM + kn + c0);
            b1 = *(const float4*)(Bb + (size_t)(r0 + 64) * DIM + kn + c0);
        }

#pragma unroll
        for (int kk = 0; kk < 16; kk += 8) {
            // A fragments: 4 m-subtiles of 16
            unsigned int af[4][4];
#pragma unroll
            for (int mi = 0; mi < 4; ++mi) {
                int row = wm + mi * 16 + arow;
                af[mi][0] = __float_as_uint(As[buf][kk + akr][row]);
                af[mi][1] = __float_as_uint(As[buf][kk + akr][row + 8]);
                af[mi][2] = __float_as_uint(As[buf][kk + 4 + akr][row]);
                af[mi][3] = __float_as_uint(As[buf][kk + 4 + akr][row + 8]);
            }
            // B fragments: 4 n-subtiles of 8
            unsigned int bf[4][2];
#pragma unroll
            for (int ni = 0; ni < 4; ++ni) {
                int col = wn + ni * 8 + arow;
                bf[ni][0] = __float_as_uint(Bs[buf][kk + akr][col]);
                bf[ni][1] = __float_as_uint(Bs[buf][kk + 4 + akr][col]);
            }
#pragma unroll
            for (int mi = 0; mi < 4; ++mi)
#pragma unroll
                for (int ni = 0; ni < 4; ++ni) {
                    asm volatile(
                        "mma.sync.aligned.m16n8k8.row.col.f32.tf32.tf32.f32 "
                        "{%0,%1,%2,%3}, {%4,%5,%6,%7}, {%8,%9}, {%0,%1,%2,%3};"
                        : "+f"(acc[mi][ni][0]), "+f"(acc[mi][ni][1]),
                          "+f"(acc[mi][ni][2]), "+f"(acc[mi][ni][3])
                        : "r"(af[mi][0]), "r"(af[mi][1]), "r"(af[mi][2]), "r"(af[mi][3]),
                          "r"(bf[ni][0]), "r"(bf[ni][1]));
                }
        }

        if (has) {
            buf ^= 1;
            STASH(buf);
            __syncthreads();
        }
    }
#undef STASH

    // epilogue: feats = X + relu(Y)
    const float* Xb = X + (size_t)m0 * DIM + n0;
    float* Fb = g_feats + (size_t)m0 * DIM + n0;
#pragma unroll
    for (int mi = 0; mi < 4; ++mi) {
        int r  = wm + mi * 16 + (lane >> 2);
#pragma unroll
        for (int ni = 0; ni < 4; ++ni) {
            int cc = wn + ni * 8 + 2 * (lane & 3);
            {
                float2 xv = *(const float2*)(Xb + (size_t)r * DIM + cc);
                float2 o;
                o.x = xv.x + fmaxf(acc[mi][ni][0], 0.f);
                o.y = xv.y + fmaxf(acc[mi][ni][1], 0.f);
                *(float2*)(Fb + (size_t)r * DIM + cc) = o;
            }
            {
                int r2 = r + 8;
                float2 xv = *(const float2*)(Xb + (size_t)r2 * DIM + cc);
                float2 o;
                o.x = xv.x + fmaxf(acc[mi][ni][2], 0.f);
                o.y = xv.y + fmaxf(acc[mi][ni][3], 0.f);
                *(float2*)(Fb + (size_t)r2 * DIM + cc) = o;
            }
        }
    }
}

// ---------------------------------------------------------------------------
// Kernel C: inter cross-attention, per class (unchanged)
// ---------------------------------------------------------------------------
__global__ __launch_bounds__(256) void kC(const float* __restrict__ protos,
                                          const float* __restrict__ w1i,
                                          const float* __restrict__ w2i,
                                          float* __restrict__ outp)
{
    const int c = blockIdx.x;
    __shared__ __align__(16) float qs[NPRO * DIM];
    __shared__ __align__(16) float ps[NPRO * OCH];

    const int tid = threadIdx.x;
    const int lane = tid & 31;
    const int w = tid >> 5;
    const float* F = g_feats + (size_t)c * (NGRP * NSEQ) * DIM;

    {
        const float4* src = (const float4*)(protos + (size_t)c * NPRO * DIM);
        float4* dst = (float4*)qs;
        for (int i = tid; i < NPRO * DIM / 4; i += 256) dst[i] = src[i];
    }
    __syncthreads();

    for (int o = w; o < OCH; o += 8) {
        float acc[NPRO] = {0.f, 0.f, 0.f, 0.f, 0.f};
        for (int d = lane; d < DIM; d += 32) {
            float wv = w2i[(size_t)o * DIM + d];
#pragma unroll
            for (int p = 0; p < NPRO; ++p) acc[p] += qs[p * DIM + d] * wv;
        }
#pragma unroll
        for (int p = 0; p < NPRO; ++p) {
#pragma unroll
            for (int off = 16; off > 0; off >>= 1)
                acc[p] += __shfl_xor_sync(0xffffffffu, acc[p], off);
        }
        if (lane == 0) {
#pragma unroll
            for (int p = 0; p < NPRO; ++p) ps[p * OCH + o] = acc[p];
        }
    }
    __syncthreads();

    for (int d = tid; d < DIM; d += 256) {
        float acc[NPRO] = {0.f, 0.f, 0.f, 0.f, 0.f};
        for (int o = 0; o < OCH; ++o) {
            float wv = w1i[(size_t)o * DIM + d];
#pragma unroll
            for (int p = 0; p < NPRO; ++p) acc[p] += ps[p * OCH + o] * wv;
        }
#pragma unroll
        for (int p = 0; p < NPRO; ++p) qs[p * DIM + d] = acc[p];
    }
    __syncthreads();

    for (int n = w; n < 256; n += 8) {
        float acc[NPRO] = {0.f, 0.f, 0.f, 0.f, 0.f};
        const float* fr = F + (size_t)n * DIM;
        for (int d = lane; d < DIM; d += 32) {
            float fv = fr[d];
#pragma unroll
            for (int p = 0; p < NPRO; ++p) acc[p] += fv * qs[p * DIM + d];
        }
#pragma unroll
        for (int p = 0; p < NPRO; ++p) {
#pragma unroll
            for (int off = 16; off > 0; off >>= 1)
                acc[p] += __shfl_xor_sync(0xffffffffu, acc[p], off);
        }
        if (lane == 0) {
#pragma unroll
            for (int p = 0; p < NPRO; ++p) ps[p * OCH + n] = acc[p] * 0.0625f;
        }
    }
    __syncthreads();

    if (w < NPRO) {
        const int p = w;
        float mx = -1e30f;
        for (int n = lane; n < 256; n += 32) mx = fmaxf(mx, ps[p * OCH + n]);
#pragma unroll
        for (int off = 16; off > 0; off >>= 1)
            mx = fmaxf(mx, __shfl_xor_sync(0xffffffffu, mx, off));
        float sm = 0.f;
        for (int n = lane; n < 256; n += 32) {
            float e = expf(ps[p * OCH + n] - mx);
            ps[p * OCH + n] = e;
            sm += e;
        }
#pragma unroll
        for (int off = 16; off > 0; off >>= 1)
            sm += __shfl_xor_sync(0xffffffffu, sm, off);
        float inv = 1.f / sm;
        for (int n = lane; n < 256; n += 32) ps[p * OCH + n] *= inv;
    }
    __syncthreads();

    float* ob = outp + (size_t)c * NPRO * DIM;
    for (int d = tid; d < DIM; d += 256) {
        float acc[NPRO] = {0.f, 0.f, 0.f, 0.f, 0.f};
        for (int n = 0; n < 256; ++n) {
            float fv = F[(size_t)n * DIM + d];
#pragma unroll
            for (int p = 0; p < NPRO; ++p) acc[p] += ps[p * OCH + n] * fv;
        }
#pragma unroll
        for (int p = 0; p < NPRO; ++p) ob[(size_t)p * DIM + d] = acc[p];
    }
}

// ---------------------------------------------------------------------------
extern "C" void kernel_launch(void* const* d_in, const int* in_sizes, int n_in,
                              void* d_out, int out_size)
{
    const float* topk   = (const float*)d_in[0];  // [64,8,32,2048]
    const float* protos = (const float*)d_in[1];  // [64,5,2048]
    const float* w1     = (const float*)d_in[2];  // [256,2048]
    const float* trans  = (const float*)d_in[3];  // [2048,2048]
    const float* w1i    = (const float*)d_in[4];  // [256,2048]
    const float* w2i    = (const float*)d_in[5];  // [256,2048]
    float* out = (float*)d_out;

    kA<<<NCLS * NGRP, 256>>>(topk, w1);
    dim3 gB(DIM / 128, MTOT / 128);  // (16, 128)
    kB<<<gB, 256>>>(trans, topk);
    kC<<<NCLS, 256>>>(protos, w1i, w2i, out);
}

// round 4
// speedup vs baseline: 1.8431x; 1.1738x over previous
#include <cuda_runtime.h>
#include <cstdint>

// Problem constants
#define NCLS 64
#define NGRP 8
#define NSEQ 32
#define DIM  2048
#define OCH  256
#define NPRO 5
#define MTOT (NCLS * NGRP * NSEQ)   // 16384

// Scratch (device globals; no runtime allocation allowed)
__device__ float g_ctx[(size_t)MTOT * DIM];    // 134 MB
__device__ float g_feats[(size_t)MTOT * DIM];  // 134 MB
__device__ float g_e[(size_t)MTOT * OCH];      // 16.8 MB

__device__ __forceinline__ float to_tf32(float x) {
    unsigned int t;
    asm("cvt.rna.tf32.f32 %0, %1;" : "=r"(t) : "f"(x));
    return __uint_as_float(t);
}

// ---------------------------------------------------------------------------
// Kernel A1 (tf32 tensor cores): E = X @ w1^T  (M=16384, N=256, K=2048)
// Same structure as kB; plain store epilogue with row stride OCH.
// ---------------------------------------------------------------------------
__global__ __launch_bounds__(256) void kA1(const float* __restrict__ Xin,
                                           const float* __restrict__ w1)
{
    __shared__ __align__(16) float As[2][16][136];
    __shared__ __align__(16) float Bs[2][16][136];

    const int tid  = threadIdx.x;
    const int lane = tid & 31;
    const int wid  = tid >> 5;
    const int wm   = (wid & 1) * 64;
    const int wn   = (wid >> 1) * 32;

    const int m0 = blockIdx.y * 128;
    const int n0 = blockIdx.x * 128;

    const float* Ab = Xin + (size_t)m0 * DIM;
    const float* Bb = w1 + (size_t)n0 * DIM;

    const int r0 = tid >> 2;
    const int c0 = (tid & 3) * 4;

    float4 a0, a1, b0, b1;

    a0 = *(const float4*)(Ab + (size_t)r0 * DIM + c0);
    a1 = *(const float4*)(Ab + (size_t)(r0 + 64) * DIM + c0);
    b0 = *(const float4*)(Bb + (size_t)r0 * DIM + c0);
    b1 = *(const float4*)(Bb + (size_t)(r0 + 64) * DIM + c0);

#define STASH(buf_) do {                                                        \
    As[buf_][c0 + 0][r0] = to_tf32(a0.x); As[buf_][c0 + 1][r0] = to_tf32(a0.y); \
    As[buf_][c0 + 2][r0] = to_tf32(a0.z); As[buf_][c0 + 3][r0] = to_tf32(a0.w); \
    As[buf_][c0 + 0][r0 + 64] = to_tf32(a1.x); As[buf_][c0 + 1][r0 + 64] = to_tf32(a1.y); \
    As[buf_][c0 + 2][r0 + 64] = to_tf32(a1.z); As[buf_][c0 + 3][r0 + 64] = to_tf32(a1.w); \
    Bs[buf_][c0 + 0][r0] = to_tf32(b0.x); Bs[buf_][c0 + 1][r0] = to_tf32(b0.y); \
    Bs[buf_][c0 + 2][r0] = to_tf32(b0.z); Bs[buf_][c0 + 3][r0] = to_tf32(b0.w); \
    Bs[buf_][c0 + 0][r0 + 64] = to_tf32(b1.x); Bs[buf_][c0 + 1][r0 + 64] = to_tf32(b1.y); \
    Bs[buf_][c0 + 2][r0 + 64] = to_tf32(b1.z); Bs[buf_][c0 + 3][r0 + 64] = to_tf32(b1.w); \
} while (0)

    STASH(0);
    __syncthreads();

    float acc[4][4][4];
#pragma unroll
    for (int mi = 0; mi < 4; ++mi)
#pragma unroll
        for (int ni = 0; ni < 4; ++ni)
#pragma unroll
            for (int r = 0; r < 4; ++r) acc[mi][ni][r] = 0.f;

    const int arow = lane >> 2;
    const int akr  = lane & 3;

    const int NKT = DIM / 16;
    int buf = 0;
    for (int kt = 0; kt < NKT; ++kt) {
        const bool has = (kt + 1) < NKT;
        if (has) {
            int kn = (kt + 1) * 16;
            a0 = *(const float4*)(Ab + (size_t)r0 * DIM + kn + c0);
            a1 = *(const float4*)(Ab + (size_t)(r0 + 64) * DIM + kn + c0);
            b0 = *(const float4*)(Bb + (size_t)r0 * DIM + kn + c0);
            b1 = *(const float4*)(Bb + (size_t)(r0 + 64) * DIM + kn + c0);
        }

#pragma unroll
        for (int kk = 0; kk < 16; kk += 8) {
            unsigned int af[4][4];
#pragma unroll
            for (int mi = 0; mi < 4; ++mi) {
                int row = wm + mi * 16 + arow;
                af[mi][0] = __float_as_uint(As[buf][kk + akr][row]);
                af[mi][1] = __float_as_uint(As[buf][kk + akr][row + 8]);
                af[mi][2] = __float_as_uint(As[buf][kk + 4 + akr][row]);
                af[mi][3] = __float_as_uint(As[buf][kk + 4 + akr][row + 8]);
            }
            unsigned int bf[4][2];
#pragma unroll
            for (int ni = 0; ni < 4; ++ni) {
                int col = wn + ni * 8 + arow;
                bf[ni][0] = __float_as_uint(Bs[buf][kk + akr][col]);
                bf[ni][1] = __float_as_uint(Bs[buf][kk + 4 + akr][col]);
            }
#pragma unroll
            for (int mi = 0; mi < 4; ++mi)
#pragma unroll
                for (int ni = 0; ni < 4; ++ni) {
                    asm volatile(
                        "mma.sync.aligned.m16n8k8.row.col.f32.tf32.tf32.f32 "
                        "{%0,%1,%2,%3}, {%4,%5,%6,%7}, {%8,%9}, {%0,%1,%2,%3};"
                        : "+f"(acc[mi][ni][0]), "+f"(acc[mi][ni][1]),
                          "+f"(acc[mi][ni][2]), "+f"(acc[mi][ni][3])
                        : "r"(af[mi][0]), "r"(af[mi][1]), "r"(af[mi][2]), "r"(af[mi][3]),
                          "r"(bf[ni][0]), "r"(bf[ni][1]));
                }
        }

        if (has) {
            buf ^= 1;
            STASH(buf);
            __syncthreads();
        }
    }
#undef STASH

    float* Eb = g_e + (size_t)m0 * OCH + n0;
#pragma unroll
    for (int mi = 0; mi < 4; ++mi) {
        int r = wm + mi * 16 + (lane >> 2);
#pragma unroll
        for (int ni = 0; ni < 4; ++ni) {
            int cc = wn + ni * 8 + 2 * (lane & 3);
            *(float2*)(Eb + (size_t)r * OCH + cc) = make_float2(acc[mi][ni][0], acc[mi][ni][1]);
            *(float2*)(Eb + (size_t)(r + 8) * OCH + cc) = make_float2(acc[mi][ni][2], acc[mi][ni][3]);
        }
    }
}

// ---------------------------------------------------------------------------
// Kernel A2: per (class, group): scores from E, softmax, ctx = att @ X
// ---------------------------------------------------------------------------
__global__ __launch_bounds__(256) void kA2(const float* __restrict__ Xall)
{
    const int blk = blockIdx.x;  // c*8+g
    const float* X  = Xall + (size_t)blk * NSEQ * DIM;
    const float* E  = g_e + (size_t)blk * NSEQ * OCH;
    float* CTX      = g_ctx + (size_t)blk * NSEQ * DIM;

    __shared__ __align__(16) float Ws[32][260];   // E tile; reused as Xc
    __shared__ __align__(16) float Ss[32][32];    // scores -> att

    const int tid = threadIdx.x;

    // Load E [32,256] into Ws (coalesced float4)
#pragma unroll
    for (int r = 0; r < 8; ++r) {
        int idx = r * 256 + tid;          // 0..2047 float4 units
        int row = idx >> 6;               // /64
        int c4  = idx & 63;
        float4 v = *(const float4*)(E + (size_t)row * OCH + c4 * 4);
        *(float4*)&Ws[row][c4 * 4] = v;
    }
    __syncthreads();

    // scores S[n][m] = (1/16) * sum_o E[n][o] E[m][o]
    {
        int n = tid >> 3;
        int mbase = (tid & 7) * 4;
        float s0 = 0.f, s1 = 0.f, s2 = 0.f, s3 = 0.f;
        for (int o = 0; o < OCH; o += 4) {
            float4 a  = *(const float4*)&Ws[n][o];
            float4 b0 = *(const float4*)&Ws[mbase + 0][o];
            float4 b1 = *(const float4*)&Ws[mbase + 1][o];
            float4 b2 = *(const float4*)&Ws[mbase + 2][o];
            float4 b3 = *(const float4*)&Ws[mbase + 3][o];
            s0 += a.x * b0.x + a.y * b0.y + a.z * b0.z + a.w * b0.w;
            s1 += a.x * b1.x + a.y * b1.y + a.z * b1.z + a.w * b1.w;
            s2 += a.x * b2.x + a.y * b2.y + a.z * b2.z + a.w * b2.w;
            s3 += a.x * b3.x + a.y * b3.y + a.z * b3.z + a.w * b3.w;
        }
        Ss[n][mbase + 0] = s0 * 0.0625f;
        Ss[n][mbase + 1] = s1 * 0.0625f;
        Ss[n][mbase + 2] = s2 * 0.0625f;
        Ss[n][mbase + 3] = s3 * 0.0625f;
    }
    __syncthreads();

    // softmax over m (rows of Ss), in place
    {
        int w = tid >> 5, lane = tid & 31;
#pragma unroll
        for (int rr = 0; rr < 4; ++rr) {
            int n = w * 4 + rr;
            float v = Ss[n][lane];
            float mx = v;
#pragma unroll
            for (int off = 16; off > 0; off >>= 1)
                mx = fmaxf(mx, __shfl_xor_sync(0xffffffffu, mx, off));
            float ex = expf(v - mx);
            float sm = ex;
#pragma unroll
            for (int off = 16; off > 0; off >>= 1)
                sm += __shfl_xor_sync(0xffffffffu, sm, off);
            Ss[n][lane] = ex / sm;
        }
    }
    __syncthreads();

    // ctx[n][d] = sum_m att[n][m] X[m][d]
    float* Xc = &Ws[0][0];
    const int XCS = 68;
    const int txc = tid & 63;
    const int tyc = tid >> 6;

    for (int d0 = 0; d0 < DIM; d0 += 64) {
#pragma unroll
        for (int r = 0; r < 2; ++r) {
            int idx = r * 256 + tid;
            int row = idx >> 4, c4 = idx & 15;
            float4 v = *(const float4*)(X + (size_t)row * DIM + d0 + c4 * 4);
            *(float4*)&Xc[row * XCS + c4 * 4] = v;
        }
        __syncthreads();

        float outv[8];
#pragma unroll
        for (int i = 0; i < 8; ++i) outv[i] = 0.f;

#pragma unroll
        for (int m4 = 0; m4 < 32; m4 += 4) {
            float xv0 = Xc[(m4 + 0) * XCS + txc];
            float xv1 = Xc[(m4 + 1) * XCS + txc];
            float xv2 = Xc[(m4 + 2) * XCS + txc];
            float xv3 = Xc[(m4 + 3) * XCS + txc];
#pragma unroll
            for (int i = 0; i < 8; ++i) {
                float4 a = *(const float4*)&Ss[tyc * 8 + i][m4];
                outv[i] += a.x * xv0 + a.y * xv1 + a.z * xv2 + a.w * xv3;
            }
        }
#pragma unroll
        for (int i = 0; i < 8; ++i)
            CTX[(size_t)(tyc * 8 + i) * DIM + d0 + txc] = outv[i];
        __syncthreads();
    }
}

// ---------------------------------------------------------------------------
// Kernel B (tf32 tensor cores): Y = ctx @ T^T, feats = X + relu(Y)   (unchanged)
// ---------------------------------------------------------------------------
__global__ __launch_bounds__(256) void kB(const float* __restrict__ T,
                                          const float* __restrict__ X)
{
    __shared__ __align__(16) float As[2][16][136];
    __shared__ __align__(16) float Bs[2][16][136];

    const int tid  = threadIdx.x;
    const int lane = tid & 31;
    const int wid  = tid >> 5;
    const int wm   = (wid & 1) * 64;
    const int wn   = (wid >> 1) * 32;

    const int m0 = blockIdx.y * 128;
    const int n0 = blockIdx.x * 128;

    const float* Ab = g_ctx + (size_t)m0 * DIM;
    const float* Bb = T + (size_t)n0 * DIM;

    const int r0 = tid >> 2;
    const int c0 = (tid & 3) * 4;

    float4 a0, a1, b0, b1;

    a0 = *(const float4*)(Ab + (size_t)r0 * DIM + c0);
    a1 = *(const float4*)(Ab + (size_t)(r0 + 64) * DIM + c0);
    b0 = *(const float4*)(Bb + (size_t)r0 * DIM + c0);
    b1 = *(const float4*)(Bb + (size_t)(r0 + 64) * DIM + c0);

#define STASH(buf_) do {                                                        \
    As[buf_][c0 + 0][r0] = to_tf32(a0.x); As[buf_][c0 + 1][r0] = to_tf32(a0.y); \
    As[buf_][c0 + 2][r0] = to_tf32(a0.z); As[buf_][c0 + 3][r0] = to_tf32(a0.w); \
    As[buf_][c0 + 0][r0 + 64] = to_tf32(a1.x); As[buf_][c0 + 1][r0 + 64] = to_tf32(a1.y); \
    As[buf_][c0 + 2][r0 + 64] = to_tf32(a1.z); As[buf_][c0 + 3][r0 + 64] = to_tf32(a1.w); \
    Bs[buf_][c0 + 0][r0] = to_tf32(b0.x); Bs[buf_][c0 + 1][r0] = to_tf32(b0.y); \
    Bs[buf_][c0 + 2][r0] = to_tf32(b0.z); Bs[buf_][c0 + 3][r0] = to_tf32(b0.w); \
    Bs[buf_][c0 + 0][r0 + 64] = to_tf32(b1.x); Bs[buf_][c0 + 1][r0 + 64] = to_tf32(b1.y); \
    Bs[buf_][c0 + 2][r0 + 64] = to_tf32(b1.z); Bs[buf_][c0 + 3][r0 + 64] = to_tf32(b1.w); \
} while (0)

    STASH(0);
    __syncthreads();

    float acc[4][4][4];
#pragma unroll
    for (int mi = 0; mi < 4; ++mi)
#pragma unroll
        for (int ni = 0; ni < 4; ++ni)
#pragma unroll
            for (int r = 0; r < 4; ++r) acc[mi][ni][r] = 0.f;

    const int arow = lane >> 2;
    const int akr  = lane & 3;

    const int NKT = DIM / 16;
    int buf = 0;
    for (int kt = 0; kt < NKT; ++kt) {
        const bool has = (kt + 1) < NKT;
        if (has) {
            int kn = (kt + 1) * 16;
            a0 = *(const float4*)(Ab + (size_t)r0 * DIM + kn + c0);
            a1 = *(const float4*)(Ab + (size_t)(r0 + 64) * DIM + kn + c0);
            b0 = *(const float4*)(Bb + (size_t)r0 * DIM + kn + c0);
            b1 = *(const float4*)(Bb + (size_t)(r0 + 64) * DIM + kn + c0);
        }

#pragma unroll
        for (int kk = 0; kk < 16; kk += 8) {
            unsigned int af[4][4];
#pragma unroll
            for (int mi = 0; mi < 4; ++mi) {
                int row = wm + mi * 16 + arow;
                af[mi][0] = __float_as_uint(As[buf][kk + akr][row]);
                af[mi][1] = __float_as_uint(As[buf][kk + akr][row + 8]);
                af[mi][2] = __float_as_uint(As[buf][kk + 4 + akr][row]);
                af[mi][3] = __float_as_uint(As[buf][kk + 4 + akr][row + 8]);
            }
            unsigned int bf[4][2];
#pragma unroll
            for (int ni = 0; ni < 4; ++ni) {
                int col = wn + ni * 8 + arow;
                bf[ni][0] = __float_as_uint(Bs[buf][kk + akr][col]);
                bf[ni][1] = __float_as_uint(Bs[buf][kk + 4 + akr][col]);
            }
#pragma unroll
            for (int mi = 0; mi < 4; ++mi)
#pragma unroll
                for (int ni = 0; ni < 4; ++ni) {
                    asm volatile(
                        "mma.sync.aligned.m16n8k8.row.col.f32.tf32.tf32.f32 "
                        "{%0,%1,%2,%3}, {%4,%5,%6,%7}, {%8,%9}, {%0,%1,%2,%3};"
                        : "+f"(acc[mi][ni][0]), "+f"(acc[mi][ni][1]),
                          "+f"(acc[mi][ni][2]), "+f"(acc[mi][ni][3])
                        : "r"(af[mi][0]), "r"(af[mi][1]), "r"(af[mi][2]), "r"(af[mi][3]),
                          "r"(bf[ni][0]), "r"(bf[ni][1]));
                }
        }

        if (has) {
            buf ^= 1;
            STASH(buf);
            __syncthreads();
        }
    }
#undef STASH

    const float* Xb = X + (size_t)m0 * DIM + n0;
    float* Fb = g_feats + (size_t)m0 * DIM + n0;
#pragma unroll
    for (int mi = 0; mi < 4; ++mi) {
        int r  = wm + mi * 16 + (lane >> 2);
#pragma unroll
        for (int ni = 0; ni < 4; ++ni) {
            int cc = wn + ni * 8 + 2 * (lane & 3);
            {
                float2 xv = *(const float2*)(Xb + (size_t)r * DIM + cc);
                float2 o;
                o.x = xv.x + fmaxf(acc[mi][ni][0], 0.f);
                o.y = xv.y + fmaxf(acc[mi][ni][1], 0.f);
                *(float2*)(Fb + (size_t)r * DIM + cc) = o;
            }
            {
                int r2 = r + 8;
                float2 xv = *(const float2*)(Xb + (size_t)r2 * DIM + cc);
                float2 o;
                o.x = xv.x + fmaxf(acc[mi][ni][2], 0.f);
                o.y = xv.y + fmaxf(acc[mi][ni][3], 0.f);
                *(float2*)(Fb + (size_t)r2 * DIM + cc) = o;
            }
        }
    }
}

// ---------------------------------------------------------------------------
// Kernel C: inter cross-attention, per class (unchanged)
// ---------------------------------------------------------------------------
__global__ __launch_bounds__(256) void kC(const float* __restrict__ protos,
                                          const float* __restrict__ w1i,
                                          const float* __restrict__ w2i,
                                          float* __restrict__ outp)
{
    const int c = blockIdx.x;
    __shared__ __align__(16) float qs[NPRO * DIM];
    __shared__ __align__(16) float ps[NPRO * OCH];

    const int tid = threadIdx.x;
    const int lane = tid & 31;
    const int w = tid >> 5;
    const float* F = g_feats + (size_t)c * (NGRP * NSEQ) * DIM;

    {
        const float4* src = (const float4*)(protos + (size_t)c * NPRO * DIM);
        float4* dst = (float4*)qs;
        for (int i = tid; i < NPRO * DIM / 4; i += 256) dst[i] = src[i];
    }
    __syncthreads();

    for (int o = w; o < OCH; o += 8) {
        float acc[NPRO] = {0.f, 0.f, 0.f, 0.f, 0.f};
        for (int d = lane; d < DIM; d += 32) {
            float wv = w2i[(size_t)o * DIM + d];
#pragma unroll
            for (int p = 0; p < NPRO; ++p) acc[p] += qs[p * DIM + d] * wv;
        }
#pragma unroll
        for (int p = 0; p < NPRO; ++p) {
#pragma unroll
            for (int off = 16; off > 0; off >>= 1)
                acc[p] += __shfl_xor_sync(0xffffffffu, acc[p], off);
        }
        if (lane == 0) {
#pragma unroll
            for (int p = 0; p < NPRO; ++p) ps[p * OCH + o] = acc[p];
        }
    }
    __syncthreads();

    for (int d = tid; d < DIM; d += 256) {
        float acc[NPRO] = {0.f, 0.f, 0.f, 0.f, 0.f};
        for (int o = 0; o < OCH; ++o) {
            float wv = w1i[(size_t)o * DIM + d];
#pragma unroll
            for (int p = 0; p < NPRO; ++p) acc[p] += ps[p * OCH + o] * wv;
        }
#pragma unroll
        for (int p = 0; p < NPRO; ++p) qs[p * DIM + d] = acc[p];
    }
    __syncthreads();

    for (int n = w; n < 256; n += 8) {
        float acc[NPRO] = {0.f, 0.f, 0.f, 0.f, 0.f};
        const float* fr = F + (size_t)n * DIM;
        for (int d = lane; d < DIM; d += 32) {
            float fv = fr[d];
#pragma unroll
            for (int p = 0; p < NPRO; ++p) acc[p] += fv * qs[p * DIM + d];
        }
#pragma unroll
        for (int p = 0; p < NPRO; ++p) {
#pragma unroll
            for (int off = 16; off > 0; off >>= 1)
                acc[p] += __shfl_xor_sync(0xffffffffu, acc[p], off);
        }
        if (lane == 0) {
#pragma unroll
            for (int p = 0; p < NPRO; ++p) ps[p * OCH + n] = acc[p] * 0.0625f;
        }
    }
    __syncthreads();

    if (w < NPRO) {
        const int p = w;
        float mx = -1e30f;
        for (int n = lane; n < 256; n += 32) mx = fmaxf(mx, ps[p * OCH + n]);
#pragma unroll
        for (int off = 16; off > 0; off >>= 1)
            mx = fmaxf(mx, __shfl_xor_sync(0xffffffffu, mx, off));
        float sm = 0.f;
        for (int n = lane; n < 256; n += 32) {
            float e = expf(ps[p * OCH + n] - mx);
            ps[p * OCH + n] = e;
            sm += e;
        }
#pragma unroll
        for (int off = 16; off > 0; off >>= 1)
            sm += __shfl_xor_sync(0xffffffffu, sm, off);
        float inv = 1.f / sm;
        for (int n = lane; n < 256; n += 32) ps[p * OCH + n] *= inv;
    }
    __syncthreads();

    float* ob = outp + (size_t)c * NPRO * DIM;
    for (int d = tid; d < DIM; d += 256) {
        float acc[NPRO] = {0.f, 0.f, 0.f, 0.f, 0.f};
        for (int n = 0; n < 256; ++n) {
            float fv = F[(size_t)n * DIM + d];
#pragma unroll
            for (int p = 0; p < NPRO; ++p) acc[p] += ps[p * OCH + n] * fv;
        }
#pragma unroll
        for (int p = 0; p < NPRO; ++p) ob[(size_t)p * DIM + d] = acc[p];
    }
}

// ---------------------------------------------------------------------------
extern "C" void kernel_launch(void* const* d_in, const int* in_sizes, int n_in,
                              void* d_out, int out_size)
{
    const float* topk   = (const float*)d_in[0];  // [64,8,32,2048]
    const float* protos = (const float*)d_in[1];  // [64,5,2048]
    const float* w1     = (const float*)d_in[2];  // [256,2048]
    const float* trans  = (const float*)d_in[3];  // [2048,2048]
    const float* w1i    = (const float*)d_in[4];  // [256,2048]
    const float* w2i    = (const float*)d_in[5];  // [256,2048]
    float* out = (float*)d_out;

    dim3 gA1(OCH / 128, MTOT / 128);  // (2, 128)
    kA1<<<gA1, 256>>>(topk, w1);
    kA2<<<NCLS * NGRP, 256>>>(topk);
    dim3 gB(DIM / 128, MTOT / 128);   // (16, 128)
    kB<<<gB, 256>>>(trans, topk);
    kC<<<NCLS, 256>>>(protos, w1i, w2i, out);
}

// round 5
// speedup vs baseline: 2.2598x; 1.2261x over previous
#include <cuda_runtime.h>
#include <cstdint>

// Problem constants
#define NCLS 64
#define NGRP 8
#define NSEQ 32
#define DIM  2048
#define OCH  256
#define NPRO 5
#define MTOT (NCLS * NGRP * NSEQ)   // 16384

// Scratch (device globals; no runtime allocation allowed)
__device__ float g_ctx[(size_t)MTOT * DIM];    // 134 MB
__device__ float g_feats[(size_t)MTOT * DIM];  // 134 MB
__device__ float g_e[(size_t)MTOT * OCH];      // 16.8 MB
__device__ float g_pe[(size_t)NCLS * NPRO * OCH];   // 327 KB
__device__ float g_q[(size_t)NCLS * NPRO * DIM];    // 2.6 MB
__device__ float g_s[(size_t)NCLS * NPRO * OCH];    // s[c][p][n], 327 KB

__device__ __forceinline__ float to_tf32(float x) {
    unsigned int t;
    asm("cvt.rna.tf32.f32 %0, %1;" : "=r"(t) : "f"(x));
    return __uint_as_float(t);
}

// ---------------------------------------------------------------------------
// Kernel A1 (tf32 tensor cores): E = X @ w1^T  (unchanged)
// ---------------------------------------------------------------------------
__global__ __launch_bounds__(256) void kA1(const float* __restrict__ Xin,
                                           const float* __restrict__ w1)
{
    __shared__ __align__(16) float As[2][16][136];
    __shared__ __align__(16) float Bs[2][16][136];

    const int tid  = threadIdx.x;
    const int lane = tid & 31;
    const int wid  = tid >> 5;
    const int wm   = (wid & 1) * 64;
    const int wn   = (wid >> 1) * 32;

    const int m0 = blockIdx.y * 128;
    const int n0 = blockIdx.x * 128;

    const float* Ab = Xin + (size_t)m0 * DIM;
    const float* Bb = w1 + (size_t)n0 * DIM;

    const int r0 = tid >> 2;
    const int c0 = (tid & 3) * 4;

    float4 a0, a1, b0, b1;

    a0 = *(const float4*)(Ab + (size_t)r0 * DIM + c0);
    a1 = *(const float4*)(Ab + (size_t)(r0 + 64) * DIM + c0);
    b0 = *(const float4*)(Bb + (size_t)r0 * DIM + c0);
    b1 = *(const float4*)(Bb + (size_t)(r0 + 64) * DIM + c0);

#define STASH(buf_) do {                                                        \
    As[buf_][c0 + 0][r0] = to_tf32(a0.x); As[buf_][c0 + 1][r0] = to_tf32(a0.y); \
    As[buf_][c0 + 2][r0] = to_tf32(a0.z); As[buf_][c0 + 3][r0] = to_tf32(a0.w); \
    As[buf_][c0 + 0][r0 + 64] = to_tf32(a1.x); As[buf_][c0 + 1][r0 + 64] = to_tf32(a1.y); \
    As[buf_][c0 + 2][r0 + 64] = to_tf32(a1.z); As[buf_][c0 + 3][r0 + 64] = to_tf32(a1.w); \
    Bs[buf_][c0 + 0][r0] = to_tf32(b0.x); Bs[buf_][c0 + 1][r0] = to_tf32(b0.y); \
    Bs[buf_][c0 + 2][r0] = to_tf32(b0.z); Bs[buf_][c0 + 3][r0] = to_tf32(b0.w); \
    Bs[buf_][c0 + 0][r0 + 64] = to_tf32(b1.x); Bs[buf_][c0 + 1][r0 + 64] = to_tf32(b1.y); \
    Bs[buf_][c0 + 2][r0 + 64] = to_tf32(b1.z); Bs[buf_][c0 + 3][r0 + 64] = to_tf32(b1.w); \
} while (0)

    STASH(0);
    __syncthreads();

    float acc[4][4][4];
#pragma unroll
    for (int mi = 0; mi < 4; ++mi)
#pragma unroll
        for (int ni = 0; ni < 4; ++ni)
#pragma unroll
            for (int r = 0; r < 4; ++r) acc[mi][ni][r] = 0.f;

    const int arow = lane >> 2;
    const int akr  = lane & 3;

    const int NKT = DIM / 16;
    int buf = 0;
    for (int kt = 0; kt < NKT; ++kt) {
        const bool has = (kt + 1) < NKT;
        if (has) {
            int kn = (kt + 1) * 16;
            a0 = *(const float4*)(Ab + (size_t)r0 * DIM + kn + c0);
            a1 = *(const float4*)(Ab + (size_t)(r0 + 64) * DIM + kn + c0);
            b0 = *(const float4*)(Bb + (size_t)r0 * DIM + kn + c0);
            b1 = *(const float4*)(Bb + (size_t)(r0 + 64) * DIM + kn + c0);
        }

#pragma unroll
        for (int kk = 0; kk < 16; kk += 8) {
            unsigned int af[4][4];
#pragma unroll
            for (int mi = 0; mi < 4; ++mi) {
                int row = wm + mi * 16 + arow;
                af[mi][0] = __float_as_uint(As[buf][kk + akr][row]);
                af[mi][1] = __float_as_uint(As[buf][kk + akr][row + 8]);
                af[mi][2] = __float_as_uint(As[buf][kk + 4 + akr][row]);
                af[mi][3] = __float_as_uint(As[buf][kk + 4 + akr][row + 8]);
            }
            unsigned int bf[4][2];
#pragma unroll
            for (int ni = 0; ni < 4; ++ni) {
                int col = wn + ni * 8 + arow;
                bf[ni][0] = __float_as_uint(Bs[buf][kk + akr][col]);
                bf[ni][1] = __float_as_uint(Bs[buf][kk + 4 + akr][col]);
            }
#pragma unroll
            for (int mi = 0; mi < 4; ++mi)
#pragma unroll
                for (int ni = 0; ni < 4; ++ni) {
                    asm volatile(
                        "mma.sync.aligned.m16n8k8.row.col.f32.tf32.tf32.f32 "
                        "{%0,%1,%2,%3}, {%4,%5,%6,%7}, {%8,%9}, {%0,%1,%2,%3};"
                        : "+f"(acc[mi][ni][0]), "+f"(acc[mi][ni][1]),
                          "+f"(acc[mi][ni][2]), "+f"(acc[mi][ni][3])
                        : "r"(af[mi][0]), "r"(af[mi][1]), "r"(af[mi][2]), "r"(af[mi][3]),
                          "r"(bf[ni][0]), "r"(bf[ni][1]));
                }
        }

        if (has) {
            buf ^= 1;
            STASH(buf);
            __syncthreads();
        }
    }
#undef STASH

    float* Eb = g_e + (size_t)m0 * OCH + n0;
#pragma unroll
    for (int mi = 0; mi < 4; ++mi) {
        int r = wm + mi * 16 + (lane >> 2);
#pragma unroll
        for (int ni = 0; ni < 4; ++ni) {
            int cc = wn + ni * 8 + 2 * (lane & 3);
            *(float2*)(Eb + (size_t)r * OCH + cc) = make_float2(acc[mi][ni][0], acc[mi][ni][1]);
            *(float2*)(Eb + (size_t)(r + 8) * OCH + cc) = make_float2(acc[mi][ni][2], acc[mi][ni][3]);
        }
    }
}

// ---------------------------------------------------------------------------
// Kernel A2: per (class, group): scores from E, softmax, ctx = att @ X (unchanged)
// ---------------------------------------------------------------------------
__global__ __launch_bounds__(256) void kA2(const float* __restrict__ Xall)
{
    const int blk = blockIdx.x;
    const float* X  = Xall + (size_t)blk * NSEQ * DIM;
    const float* E  = g_e + (size_t)blk * NSEQ * OCH;
    float* CTX      = g_ctx + (size_t)blk * NSEQ * DIM;

    __shared__ __align__(16) float Ws[32][260];
    __shared__ __align__(16) float Ss[32][32];

    const int tid = threadIdx.x;

#pragma unroll
    for (int r = 0; r < 8; ++r) {
        int idx = r * 256 + tid;
        int row = idx >> 6;
        int c4  = idx & 63;
        float4 v = *(const float4*)(E + (size_t)row * OCH + c4 * 4);
        *(float4*)&Ws[row][c4 * 4] = v;
    }
    __syncthreads();

    {
        int n = tid >> 3;
        int mbase = (tid & 7) * 4;
        float s0 = 0.f, s1 = 0.f, s2 = 0.f, s3 = 0.f;
        for (int o = 0; o < OCH; o += 4) {
            float4 a  = *(const float4*)&Ws[n][o];
            float4 b0 = *(const float4*)&Ws[mbase + 0][o];
            float4 b1 = *(const float4*)&Ws[mbase + 1][o];
            float4 b2 = *(const float4*)&Ws[mbase + 2][o];
            float4 b3 = *(const float4*)&Ws[mbase + 3][o];
            s0 += a.x * b0.x + a.y * b0.y + a.z * b0.z + a.w * b0.w;
            s1 += a.x * b1.x + a.y * b1.y + a.z * b1.z + a.w * b1.w;
            s2 += a.x * b2.x + a.y * b2.y + a.z * b2.z + a.w * b2.w;
            s3 += a.x * b3.x + a.y * b3.y + a.z * b3.z + a.w * b3.w;
        }
        Ss[n][mbase + 0] = s0 * 0.0625f;
        Ss[n][mbase + 1] = s1 * 0.0625f;
        Ss[n][mbase + 2] = s2 * 0.0625f;
        Ss[n][mbase + 3] = s3 * 0.0625f;
    }
    __syncthreads();

    {
        int w = tid >> 5, lane = tid & 31;
#pragma unroll
        for (int rr = 0; rr < 4; ++rr) {
            int n = w * 4 + rr;
            float v = Ss[n][lane];
            float mx = v;
#pragma unroll
            for (int off = 16; off > 0; off >>= 1)
                mx = fmaxf(mx, __shfl_xor_sync(0xffffffffu, mx, off));
            float ex = expf(v - mx);
            float sm = ex;
#pragma unroll
            for (int off = 16; off > 0; off >>= 1)
                sm += __shfl_xor_sync(0xffffffffu, sm, off);
            Ss[n][lane] = ex / sm;
        }
    }
    __syncthreads();

    float* Xc = &Ws[0][0];
    const int XCS = 68;
    const int txc = tid & 63;
    const int tyc = tid >> 6;

    for (int d0 = 0; d0 < DIM; d0 += 64) {
#pragma unroll
        for (int r = 0; r < 2; ++r) {
            int idx = r * 256 + tid;
            int row = idx >> 4, c4 = idx & 15;
            float4 v = *(const float4*)(X + (size_t)row * DIM + d0 + c4 * 4);
            *(float4*)&Xc[row * XCS + c4 * 4] = v;
        }
        __syncthreads();

        float outv[8];
#pragma unroll
        for (int i = 0; i < 8; ++i) outv[i] = 0.f;

#pragma unroll
        for (int m4 = 0; m4 < 32; m4 += 4) {
            float xv0 = Xc[(m4 + 0) * XCS + txc];
            float xv1 = Xc[(m4 + 1) * XCS + txc];
            float xv2 = Xc[(m4 + 2) * XCS + txc];
            float xv3 = Xc[(m4 + 3) * XCS + txc];
#pragma unroll
            for (int i = 0; i < 8; ++i) {
                float4 a = *(const float4*)&Ss[tyc * 8 + i][m4];
                outv[i] += a.x * xv0 + a.y * xv1 + a.z * xv2 + a.w * xv3;
            }
        }
#pragma unroll
        for (int i = 0; i < 8; ++i)
            CTX[(size_t)(tyc * 8 + i) * DIM + d0 + txc] = outv[i];
        __syncthreads();
    }
}

// ---------------------------------------------------------------------------
// Kernel B (tf32 tensor cores): Y = ctx @ T^T, feats = X + relu(Y)   (unchanged)
// ---------------------------------------------------------------------------
__global__ __launch_bounds__(256) void kB(const float* __restrict__ T,
                                          const float* __restrict__ X)
{
    __shared__ __align__(16) float As[2][16][136];
    __shared__ __align__(16) float Bs[2][16][136];

    const int tid  = threadIdx.x;
    const int lane = tid & 31;
    const int wid  = tid >> 5;
    const int wm   = (wid & 1) * 64;
    const int wn   = (wid >> 1) * 32;

    const int m0 = blockIdx.y * 128;
    const int n0 = blockIdx.x * 128;

    const float* Ab = g_ctx + (size_t)m0 * DIM;
    const float* Bb = T + (size_t)n0 * DIM;

    const int r0 = tid >> 2;
    const int c0 = (tid & 3) * 4;

    float4 a0, a1, b0, b1;

    a0 = *(const float4*)(Ab + (size_t)r0 * DIM + c0);
    a1 = *(const float4*)(Ab + (size_t)(r0 + 64) * DIM + c0);
    b0 = *(const float4*)(Bb + (size_t)r0 * DIM + c0);
    b1 = *(const float4*)(Bb + (size_t)(r0 + 64) * DIM + c0);

#define STASH(buf_) do {                                                        \
    As[buf_][c0 + 0][r0] = to_tf32(a0.x); As[buf_][c0 + 1][r0] = to_tf32(a0.y); \
    As[buf_][c0 + 2][r0] = to_tf32(a0.z); As[buf_][c0 + 3][r0] = to_tf32(a0.w); \
    As[buf_][c0 + 0][r0 + 64] = to_tf32(a1.x); As[buf_][c0 + 1][r0 + 64] = to_tf32(a1.y); \
    As[buf_][c0 + 2][r0 + 64] = to_tf32(a1.z); As[buf_][c0 + 3][r0 + 64] = to_tf32(a1.w); \
    Bs[buf_][c0 + 0][r0] = to_tf32(b0.x); Bs[buf_][c0 + 1][r0] = to_tf32(b0.y); \
    Bs[buf_][c0 + 2][r0] = to_tf32(b0.z); Bs[buf_][c0 + 3][r0] = to_tf32(b0.w); \
    Bs[buf_][c0 + 0][r0 + 64] = to_tf32(b1.x); Bs[buf_][c0 + 1][r0 + 64] = to_tf32(b1.y); \
    Bs[buf_][c0 + 2][r0 + 64] = to_tf32(b1.z); Bs[buf_][c0 + 3][r0 + 64] = to_tf32(b1.w); \
} while (0)

    STASH(0);
    __syncthreads();

    float acc[4][4][4];
#pragma unroll
    for (int mi = 0; mi < 4; ++mi)
#pragma unroll
        for (int ni = 0; ni < 4; ++ni)
#pragma unroll
            for (int r = 0; r < 4; ++r) acc[mi][ni][r] = 0.f;

    const int arow = lane >> 2;
    const int akr  = lane & 3;

    const int NKT = DIM / 16;
    int buf = 0;
    for (int kt = 0; kt < NKT; ++kt) {
        const bool has = (kt + 1) < NKT;
        if (has) {
            int kn = (kt + 1) * 16;
            a0 = *(const float4*)(Ab + (size_t)r0 * DIM + kn + c0);
            a1 = *(const float4*)(Ab + (size_t)(r0 + 64) * DIM + kn + c0);
            b0 = *(const float4*)(Bb + (size_t)r0 * DIM + kn + c0);
            b1 = *(const float4*)(Bb + (size_t)(r0 + 64) * DIM + kn + c0);
        }

#pragma unroll
        for (int kk = 0; kk < 16; kk += 8) {
            unsigned int af[4][4];
#pragma unroll
            for (int mi = 0; mi < 4; ++mi) {
                int row = wm + mi * 16 + arow;
                af[mi][0] = __float_as_uint(As[buf][kk + akr][row]);
                af[mi][1] = __float_as_uint(As[buf][kk + akr][row + 8]);
                af[mi][2] = __float_as_uint(As[buf][kk + 4 + akr][row]);
                af[mi][3] = __float_as_uint(As[buf][kk + 4 + akr][row + 8]);
            }
            unsigned int bf[4][2];
#pragma unroll
            for (int ni = 0; ni < 4; ++ni) {
                int col = wn + ni * 8 + arow;
                bf[ni][0] = __float_as_uint(Bs[buf][kk + akr][col]);
                bf[ni][1] = __float_as_uint(Bs[buf][kk + 4 + akr][col]);
            }
#pragma unroll
            for (int mi = 0; mi < 4; ++mi)
#pragma unroll
                for (int ni = 0; ni < 4; ++ni) {
                    asm volatile(
                        "mma.sync.aligned.m16n8k8.row.col.f32.tf32.tf32.f32 "
                        "{%0,%1,%2,%3}, {%4,%5,%6,%7}, {%8,%9}, {%0,%1,%2,%3};"
                        : "+f"(acc[mi][ni][0]), "+f"(acc[mi][ni][1]),
                          "+f"(acc[mi][ni][2]), "+f"(acc[mi][ni][3])
                        : "r"(af[mi][0]), "r"(af[mi][1]), "r"(af[mi][2]), "r"(af[mi][3]),
                          "r"(bf[ni][0]), "r"(bf[ni][1]));
                }
        }

        if (has) {
            buf ^= 1;
            STASH(buf);
            __syncthreads();
        }
    }
#undef STASH

    const float* Xb = X + (size_t)m0 * DIM + n0;
    float* Fb = g_feats + (size_t)m0 * DIM + n0;
#pragma unroll
    for (int mi = 0; mi < 4; ++mi) {
        int r  = wm + mi * 16 + (lane >> 2);
#pragma unroll
        for (int ni = 0; ni < 4; ++ni) {
            int cc = wn + ni * 8 + 2 * (lane & 3);
            {
                float2 xv = *(const float2*)(Xb + (size_t)r * DIM + cc);
                float2 o;
                o.x = xv.x + fmaxf(acc[mi][ni][0], 0.f);
                o.y = xv.y + fmaxf(acc[mi][ni][1], 0.f);
                *(float2*)(Fb + (size_t)r * DIM + cc) = o;
            }
            {
                int r2 = r + 8;
                float2 xv = *(const float2*)(Xb + (size_t)r2 * DIM + cc);
                float2 o;
                o.x = xv.x + fmaxf(acc[mi][ni][2], 0.f);
                o.y = xv.y + fmaxf(acc[mi][ni][3], 0.f);
                *(float2*)(Fb + (size_t)r2 * DIM + cc) = o;
            }
        }
    }
}

// ---------------------------------------------------------------------------
// kC1: p_e[c][p][o] = protos[c,p,:] . w2i[o,:]
// grid (8, 64): blockIdx.x = o-chunk (32 o's), blockIdx.y = class.
// ---------------------------------------------------------------------------
__global__ __launch_bounds__(256) void kC1(const float* __restrict__ protos,
                                           const float* __restrict__ w2i)
{
    const int c  = blockIdx.y;
    const int o0 = blockIdx.x * 32;
    __shared__ __align__(16) float prs[NPRO * DIM];  // 40 KB

    const int tid = threadIdx.x;
    const int lane = tid & 31;
    const int w = tid >> 5;

    {
        const float4* src = (const float4*)(protos + (size_t)c * NPRO * DIM);
        float4* dst = (float4*)prs;
        for (int i = tid; i < NPRO * DIM / 4; i += 256) dst[i] = src[i];
    }
    __syncthreads();

#pragma unroll
    for (int oi = 0; oi < 4; ++oi) {
        int o = o0 + w * 4 + oi;
        float acc[NPRO] = {0.f, 0.f, 0.f, 0.f, 0.f};
        for (int d = lane; d < DIM; d += 32) {
            float wv = w2i[(size_t)o * DIM + d];
#pragma unroll
            for (int p = 0; p < NPRO; ++p) acc[p] += prs[p * DIM + d] * wv;
        }
#pragma unroll
        for (int p = 0; p < NPRO; ++p) {
#pragma unroll
            for (int off = 16; off > 0; off >>= 1)
                acc[p] += __shfl_xor_sync(0xffffffffu, acc[p], off);
        }
        if (lane == 0) {
#pragma unroll
            for (int p = 0; p < NPRO; ++p)
                g_pe[((size_t)c * NPRO + p) * OCH + o] = acc[p];
        }
    }
}

// ---------------------------------------------------------------------------
// kC2: q[c][p][d] = sum_o p_e[c][p][o] * w1i[o][d]
// grid (8, 64): blockIdx.x = d-chunk (256 wide), blockIdx.y = class.
// ---------------------------------------------------------------------------
__global__ __launch_bounds__(256) void kC2(const float* __restrict__ w1i)
{
    const int c  = blockIdx.y;
    const int d0 = blockIdx.x * 256;
    __shared__ __align__(16) float pes[NPRO * OCH];

    const int tid = threadIdx.x;
    {
        const float4* src = (const float4*)(g_pe + (size_t)c * NPRO * OCH);
        float4* dst = (float4*)pes;
        for (int i = tid; i < NPRO * OCH / 4; i += 256) dst[i] = src[i];
    }
    __syncthreads();

    const int d = d0 + tid;
    float acc[NPRO] = {0.f, 0.f, 0.f, 0.f, 0.f};
#pragma unroll 4
    for (int o = 0; o < OCH; ++o) {
        float wv = w1i[(size_t)o * DIM + d];
#pragma unroll
        for (int p = 0; p < NPRO; ++p) acc[p] += pes[p * OCH + o] * wv;
    }
#pragma unroll
    for (int p = 0; p < NPRO; ++p)
        g_q[((size_t)c * NPRO + p) * DIM + d] = acc[p];
}

// ---------------------------------------------------------------------------
// kC3: s[c][p][n] = (1/16) * feats[c,n,:] . q[c,p,:]
// grid (8, 64): blockIdx.x = n-chunk (32 rows), blockIdx.y = class.
// ---------------------------------------------------------------------------
__global__ __launch_bounds__(256) void kC3()
{
    const int c  = blockIdx.y;
    const int n0 = blockIdx.x * 32;
    __shared__ __align__(16) float qsm[NPRO * DIM];  // 40 KB

    const int tid = threadIdx.x;
    const int lane = tid & 31;
    const int w = tid >> 5;
    const float* F = g_feats + (size_t)c * (NGRP * NSEQ) * DIM;

    {
        const float4* src = (const float4*)(g_q + (size_t)c * NPRO * DIM);
        float4* dst = (float4*)qsm;
        for (int i = tid; i < NPRO * DIM / 4; i += 256) dst[i] = src[i];
    }
    __syncthreads();

#pragma unroll
    for (int ni = 0; ni < 4; ++ni) {
        int n = n0 + w * 4 + ni;
        const float* fr = F + (size_t)n * DIM;
        float acc[NPRO] = {0.f, 0.f, 0.f, 0.f, 0.f};
        for (int d = lane; d < DIM; d += 32) {
            float fv = fr[d];
#pragma unroll
            for (int p = 0; p < NPRO; ++p) acc[p] += fv * qsm[p * DIM + d];
        }
#pragma unroll
        for (int p = 0; p < NPRO; ++p) {
#pragma unroll
            for (int off = 16; off > 0; off >>= 1)
                acc[p] += __shfl_xor_sync(0xffffffffu, acc[p], off);
        }
        if (lane == 0) {
#pragma unroll
            for (int p = 0; p < NPRO; ++p)
                g_s[((size_t)c * NPRO + p) * OCH + n] = acc[p] * 0.0625f;
        }
    }
}

// ---------------------------------------------------------------------------
// kC4: softmax over n (recomputed per block, cheap) + out = att2 @ feats
// grid (8, 64): blockIdx.x = d-chunk (256 wide), blockIdx.y = class.
// ---------------------------------------------------------------------------
__global__ __launch_bounds__(256) void kC4(float* __restrict__ outp)
{
    const int c  = blockIdx.y;
    const int d0 = blockIdx.x * 256;
    __shared__ __align__(16) float att[NPRO * OCH];  // att[p][n]

    const int tid = threadIdx.x;
    const int lane = tid & 31;
    const int w = tid >> 5;
    const float* F = g_feats + (size_t)c * (NGRP * NSEQ) * DIM;

    {
        const float4* src = (const float4*)(g_s + (size_t)c * NPRO * OCH);
        float4* dst = (float4*)att;
        for (int i = tid; i < NPRO * OCH / 4; i += 256) dst[i] = src[i];
    }
    __syncthreads();

    // softmax over n per prototype (warps 0..4), matching previous reduction order
    if (w < NPRO) {
        const int p = w;
        float mx = -1e30f;
        for (int n = lane; n < OCH; n += 32) mx = fmaxf(mx, att[p * OCH + n]);
#pragma unroll
        for (int off = 16; off > 0; off >>= 1)
            mx = fmaxf(mx, __shfl_xor_sync(0xffffffffu, mx, off));
        float sm = 0.f;
        for (int n = lane; n < OCH; n += 32) {
            float e = expf(att[p * OCH + n] - mx);
            att[p * OCH + n] = e;
            sm += e;
        }
#pragma unroll
        for (int off = 16; off > 0; off >>= 1)
            sm += __shfl_xor_sync(0xffffffffu, sm, off);
        float inv = 1.f / sm;
        for (int n = lane; n < OCH; n += 32) att[p * OCH + n] *= inv;
    }
    __syncthreads();

    const int d = d0 + tid;
    float acc[NPRO] = {0.f, 0.f, 0.f, 0.f, 0.f};
#pragma unroll 4
    for (int n = 0; n < OCH; ++n) {
        float fv = F[(size_t)n * DIM + d];
#pragma unroll
        for (int p = 0; p < NPRO; ++p) acc[p] += att[p * OCH + n] * fv;
    }
    float* ob = outp + (size_t)c * NPRO * DIM;
#pragma unroll
    for (int p = 0; p < NPRO; ++p) ob[(size_t)p * DIM + d] = acc[p];
}

// ---------------------------------------------------------------------------
extern "C" void kernel_launch(void* const* d_in, const int* in_sizes, int n_in,
                              void* d_out, int out_size)
{
    const float* topk   = (const float*)d_in[0];  // [64,8,32,2048]
    const float* protos = (const float*)d_in[1];  // [64,5,2048]
    const float* w1     = (const float*)d_in[2];  // [256,2048]
    const float* trans  = (const float*)d_in[3];  // [2048,2048]
    const float* w1i    = (const float*)d_in[4];  // [256,2048]
    const float* w2i    = (const float*)d_in[5];  // [256,2048]
    float* out = (float*)d_out;

    dim3 gA1(OCH / 128, MTOT / 128);  // (2, 128)
    kA1<<<gA1, 256>>>(topk, w1);
    kA2<<<NCLS * NGRP, 256>>>(topk);
    dim3 gB(DIM / 128, MTOT / 128);   // (16, 128)
    kB<<<gB, 256>>>(trans, topk);

    dim3 gC(8, NCLS);                 // (8, 64)
    kC1<<<gC, 256>>>(protos, w2i);
    kC2<<<gC, 256>>>(w1i);
    kC3<<<gC, 256>>>();
    kC4<<<gC, 256>>>(out);
}

// round 6
// speedup vs baseline: 3.1490x; 1.3935x over previous
#include <cuda_runtime.h>
#include <cstdint>

// Problem constants
#define NCLS 64
#define NGRP 8
#define NSEQ 32
#define DIM  2048
#define OCH  256
#define NPRO 5
#define MTOT (NCLS * NGRP * NSEQ)   // 16384

// Scratch (device globals; no runtime allocation allowed)
__device__ float g_ctx[(size_t)MTOT * DIM];    // 134 MB
__device__ float g_feats[(size_t)MTOT * DIM];  // 134 MB
__device__ float g_e[(size_t)MTOT * OCH];      // 16.8 MB
__device__ float g_pe[(size_t)NCLS * NPRO * OCH];   // 327 KB
__device__ float g_q[(size_t)NCLS * NPRO * DIM];    // 2.6 MB
__device__ float g_s[(size_t)NCLS * NPRO * OCH];    // s[c][p][n], 327 KB

__device__ __forceinline__ float to_tf32(float x) {
    unsigned int t;
    asm("cvt.rna.tf32.f32 %0, %1;" : "=r"(t) : "f"(x));
    return __uint_as_float(t);
}

// ---------------------------------------------------------------------------
// Kernel A1 (tf32 tensor cores): E = X @ w1^T  (unchanged)
// ---------------------------------------------------------------------------
__global__ __launch_bounds__(256) void kA1(const float* __restrict__ Xin,
                                           const float* __restrict__ w1)
{
    __shared__ __align__(16) float As[2][16][136];
    __shared__ __align__(16) float Bs[2][16][136];

    const int tid  = threadIdx.x;
    const int lane = tid & 31;
    const int wid  = tid >> 5;
    const int wm   = (wid & 1) * 64;
    const int wn   = (wid >> 1) * 32;

    const int m0 = blockIdx.y * 128;
    const int n0 = blockIdx.x * 128;

    const float* Ab = Xin + (size_t)m0 * DIM;
    const float* Bb = w1 + (size_t)n0 * DIM;

    const int r0 = tid >> 2;
    const int c0 = (tid & 3) * 4;

    float4 a0, a1, b0, b1;

    a0 = *(const float4*)(Ab + (size_t)r0 * DIM + c0);
    a1 = *(const float4*)(Ab + (size_t)(r0 + 64) * DIM + c0);
    b0 = *(const float4*)(Bb + (size_t)r0 * DIM + c0);
    b1 = *(const float4*)(Bb + (size_t)(r0 + 64) * DIM + c0);

#define STASH(buf_) do {                                                        \
    As[buf_][c0 + 0][r0] = to_tf32(a0.x); As[buf_][c0 + 1][r0] = to_tf32(a0.y); \
    As[buf_][c0 + 2][r0] = to_tf32(a0.z); As[buf_][c0 + 3][r0] = to_tf32(a0.w); \
    As[buf_][c0 + 0][r0 + 64] = to_tf32(a1.x); As[buf_][c0 + 1][r0 + 64] = to_tf32(a1.y); \
    As[buf_][c0 + 2][r0 + 64] = to_tf32(a1.z); As[buf_][c0 + 3][r0 + 64] = to_tf32(a1.w); \
    Bs[buf_][c0 + 0][r0] = to_tf32(b0.x); Bs[buf_][c0 + 1][r0] = to_tf32(b0.y); \
    Bs[buf_][c0 + 2][r0] = to_tf32(b0.z); Bs[buf_][c0 + 3][r0] = to_tf32(b0.w); \
    Bs[buf_][c0 + 0][r0 + 64] = to_tf32(b1.x); Bs[buf_][c0 + 1][r0 + 64] = to_tf32(b1.y); \
    Bs[buf_][c0 + 2][r0 + 64] = to_tf32(b1.z); Bs[buf_][c0 + 3][r0 + 64] = to_tf32(b1.w); \
} while (0)

    STASH(0);
    __syncthreads();

    float acc[4][4][4];
#pragma unroll
    for (int mi = 0; mi < 4; ++mi)
#pragma unroll
        for (int ni = 0; ni < 4; ++ni)
#pragma unroll
            for (int r = 0; r < 4; ++r) acc[mi][ni][r] = 0.f;

    const int arow = lane >> 2;
    const int akr  = lane & 3;

    const int NKT = DIM / 16;
    int buf = 0;
    for (int kt = 0; kt < NKT; ++kt) {
        const bool has = (kt + 1) < NKT;
        if (has) {
            int kn = (kt + 1) * 16;
            a0 = *(const float4*)(Ab + (size_t)r0 * DIM + kn + c0);
            a1 = *(const float4*)(Ab + (size_t)(r0 + 64) * DIM + kn + c0);
            b0 = *(const float4*)(Bb + (size_t)r0 * DIM + kn + c0);
            b1 = *(const float4*)(Bb + (size_t)(r0 + 64) * DIM + kn + c0);
        }

#pragma unroll
        for (int kk = 0; kk < 16; kk += 8) {
            unsigned int af[4][4];
#pragma unroll
            for (int mi = 0; mi < 4; ++mi) {
                int row = wm + mi * 16 + arow;
                af[mi][0] = __float_as_uint(As[buf][kk + akr][row]);
                af[mi][1] = __float_as_uint(As[buf][kk + akr][row + 8]);
                af[mi][2] = __float_as_uint(As[buf][kk + 4 + akr][row]);
                af[mi][3] = __float_as_uint(As[buf][kk + 4 + akr][row + 8]);
            }
            unsigned int bf[4][2];
#pragma unroll
            for (int ni = 0; ni < 4; ++ni) {
                int col = wn + ni * 8 + arow;
                bf[ni][0] = __float_as_uint(Bs[buf][kk + akr][col]);
                bf[ni][1] = __float_as_uint(Bs[buf][kk + 4 + akr][col]);
            }
#pragma unroll
            for (int mi = 0; mi < 4; ++mi)
#pragma unroll
                for (int ni = 0; ni < 4; ++ni) {
                    asm volatile(
                        "mma.sync.aligned.m16n8k8.row.col.f32.tf32.tf32.f32 "
                        "{%0,%1,%2,%3}, {%4,%5,%6,%7}, {%8,%9}, {%0,%1,%2,%3};"
                        : "+f"(acc[mi][ni][0]), "+f"(acc[mi][ni][1]),
                          "+f"(acc[mi][ni][2]), "+f"(acc[mi][ni][3])
                        : "r"(af[mi][0]), "r"(af[mi][1]), "r"(af[mi][2]), "r"(af[mi][3]),
                          "r"(bf[ni][0]), "r"(bf[ni][1]));
                }
        }

        if (has) {
            buf ^= 1;
            STASH(buf);
            __syncthreads();
        }
    }
#undef STASH

    float* Eb = g_e + (size_t)m0 * OCH + n0;
#pragma unroll
    for (int mi = 0; mi < 4; ++mi) {
        int r = wm + mi * 16 + (lane >> 2);
#pragma unroll
        for (int ni = 0; ni < 4; ++ni) {
            int cc = wn + ni * 8 + 2 * (lane & 3);
            *(float2*)(Eb + (size_t)r * OCH + cc) = make_float2(acc[mi][ni][0], acc[mi][ni][1]);
            *(float2*)(Eb + (size_t)(r + 8) * OCH + cc) = make_float2(acc[mi][ni][2], acc[mi][ni][3]);
        }
    }
}

// ---------------------------------------------------------------------------
// Kernel A2: per (class, group): scores from E, softmax, ctx = att @ X (unchanged)
// ---------------------------------------------------------------------------
__global__ __launch_bounds__(256) void kA2(const float* __restrict__ Xall)
{
    const int blk = blockIdx.x;
    const float* X  = Xall + (size_t)blk * NSEQ * DIM;
    const float* E  = g_e + (size_t)blk * NSEQ * OCH;
    float* CTX      = g_ctx + (size_t)blk * NSEQ * DIM;

    __shared__ __align__(16) float Ws[32][260];
    __shared__ __align__(16) float Ss[32][32];

    const int tid = threadIdx.x;

#pragma unroll
    for (int r = 0; r < 8; ++r) {
        int idx = r * 256 + tid;
        int row = idx >> 6;
        int c4  = idx & 63;
        float4 v = *(const float4*)(E + (size_t)row * OCH + c4 * 4);
        *(float4*)&Ws[row][c4 * 4] = v;
    }
    __syncthreads();

    {
        int n = tid >> 3;
        int mbase = (tid & 7) * 4;
        float s0 = 0.f, s1 = 0.f, s2 = 0.f, s3 = 0.f;
        for (int o = 0; o < OCH; o += 4) {
            float4 a  = *(const float4*)&Ws[n][o];
            float4 b0 = *(const float4*)&Ws[mbase + 0][o];
            float4 b1 = *(const float4*)&Ws[mbase + 1][o];
            float4 b2 = *(const float4*)&Ws[mbase + 2][o];
            float4 b3 = *(const float4*)&Ws[mbase + 3][o];
            s0 += a.x * b0.x + a.y * b0.y + a.z * b0.z + a.w * b0.w;
            s1 += a.x * b1.x + a.y * b1.y + a.z * b1.z + a.w * b1.w;
            s2 += a.x * b2.x + a.y * b2.y + a.z * b2.z + a.w * b2.w;
            s3 += a.x * b3.x + a.y * b3.y + a.z * b3.z + a.w * b3.w;
        }
        Ss[n][mbase + 0] = s0 * 0.0625f;
        Ss[n][mbase + 1] = s1 * 0.0625f;
        Ss[n][mbase + 2] = s2 * 0.0625f;
        Ss[n][mbase + 3] = s3 * 0.0625f;
    }
    __syncthreads();

    {
        int w = tid >> 5, lane = tid & 31;
#pragma unroll
        for (int rr = 0; rr < 4; ++rr) {
            int n = w * 4 + rr;
            float v = Ss[n][lane];
            float mx = v;
#pragma unroll
            for (int off = 16; off > 0; off >>= 1)
                mx = fmaxf(mx, __shfl_xor_sync(0xffffffffu, mx, off));
            float ex = expf(v - mx);
            float sm = ex;
#pragma unroll
            for (int off = 16; off > 0; off >>= 1)
                sm += __shfl_xor_sync(0xffffffffu, sm, off);
            Ss[n][lane] = ex / sm;
        }
    }
    __syncthreads();

    float* Xc = &Ws[0][0];
    const int XCS = 68;
    const int txc = tid & 63;
    const int tyc = tid >> 6;

    for (int d0 = 0; d0 < DIM; d0 += 64) {
#pragma unroll
        for (int r = 0; r < 2; ++r) {
            int idx = r * 256 + tid;
            int row = idx >> 4, c4 = idx & 15;
            float4 v = *(const float4*)(X + (size_t)row * DIM + d0 + c4 * 4);
            *(float4*)&Xc[row * XCS + c4 * 4] = v;
        }
        __syncthreads();

        float outv[8];
#pragma unroll
        for (int i = 0; i < 8; ++i) outv[i] = 0.f;

#pragma unroll
        for (int m4 = 0; m4 < 32; m4 += 4) {
            float xv0 = Xc[(m4 + 0) * XCS + txc];
            float xv1 = Xc[(m4 + 1) * XCS + txc];
            float xv2 = Xc[(m4 + 2) * XCS + txc];
            float xv3 = Xc[(m4 + 3) * XCS + txc];
#pragma unroll
            for (int i = 0; i < 8; ++i) {
                float4 a = *(const float4*)&Ss[tyc * 8 + i][m4];
                outv[i] += a.x * xv0 + a.y * xv1 + a.z * xv2 + a.w * xv3;
            }
        }
#pragma unroll
        for (int i = 0; i < 8; ++i)
            CTX[(size_t)(tyc * 8 + i) * DIM + d0 + txc] = outv[i];
        __syncthreads();
    }
}

// ---------------------------------------------------------------------------
// Kernel B v2: Y = ctx @ T^T, feats = X + relu(Y)
// cp.async (global->smem direct), [m][k] smem layout stride 20 (bank-clean),
// ldmatrix.x4 fragment loads, 2-stage pipeline, 1 sync per 16-deep k-tile.
// Raw fp32 bits fed to tf32 mma (HW truncates low mantissa bits).
// ---------------------------------------------------------------------------
#define KBS 20   // smem row stride in floats (80B, 16B-aligned, conflict-free)

__global__ __launch_bounds__(256) void kB(const float* __restrict__ T,
                                          const float* __restrict__ X)
{
    __shared__ __align__(16) float As[2][128 * KBS];
    __shared__ __align__(16) float Bs[2][128 * KBS];

    const int tid  = threadIdx.x;
    const int lane = tid & 31;
    const int wid  = tid >> 5;
    const int wm   = (wid & 1) * 64;
    const int wn   = (wid >> 1) * 32;

    const int m0 = blockIdx.y * 128;
    const int n0 = blockIdx.x * 128;

    const float* Ab = g_ctx + (size_t)m0 * DIM;
    const float* Bb = T + (size_t)n0 * DIM;

    // cp.async chunk mapping: chunk c = tid + 256*i (i=0,1); row=c>>2, q=c&3.
    const int lrow0 = tid >> 2;           // rows 0..63   (i=0)
    const int lrow1 = (tid + 256) >> 2;   // rows 64..127 (i=1)
    const int lq    = (tid & 3) * 4;      // k offset in floats

    const unsigned int sA0 = (unsigned int)__cvta_generic_to_shared(&As[0][0]);
    const unsigned int sA1 = (unsigned int)__cvta_generic_to_shared(&As[1][0]);
    const unsigned int sB0 = (unsigned int)__cvta_generic_to_shared(&Bs[0][0]);
    const unsigned int sB1 = (unsigned int)__cvta_generic_to_shared(&Bs[1][0]);

#define CPA(dst_u32, srcp) \
    asm volatile("cp.async.cg.shared.global [%0], [%1], 16;" :: "r"(dst_u32), "l"(srcp) : "memory")

#define LOAD_TILE(bufA, bufB, k0_) do {                                              \
    CPA(bufA + (unsigned)(lrow0 * KBS + lq) * 4, Ab + (size_t)lrow0 * DIM + (k0_) + lq); \
    CPA(bufA + (unsigned)(lrow1 * KBS + lq) * 4, Ab + (size_t)lrow1 * DIM + (k0_) + lq); \
    CPA(bufB + (unsigned)(lrow0 * KBS + lq) * 4, Bb + (size_t)lrow0 * DIM + (k0_) + lq); \
    CPA(bufB + (unsigned)(lrow1 * KBS + lq) * 4, Bb + (size_t)lrow1 * DIM + (k0_) + lq); \
    asm volatile("cp.async.commit_group;" ::: "memory");                             \
} while (0)

    // ldmatrix per-lane row offsets (in floats, excluding kk)
    // A (mi): mats 0..3 = (rows+0,k+0),(rows+8,k+0),(rows+0,k+4),(rows+8,k+4)
    unsigned int offA[4];
#pragma unroll
    for (int mi = 0; mi < 4; ++mi)
        offA[mi] = (unsigned)((wm + mi * 16 + ((lane >> 3) & 1) * 8 + (lane & 7)) * KBS
                              + (lane >> 4) * 4);
    // B (pair pr): mats 0..3 = (n+0,k+0),(n+0,k+4),(n+8,k+0),(n+8,k+4)
    unsigned int offB[2];
#pragma unroll
    for (int pr = 0; pr < 2; ++pr)
        offB[pr] = (unsigned)((wn + pr * 16 + ((lane >> 4) & 1) * 8 + (lane & 7)) * KBS
                              + ((lane >> 3) & 1) * 4);

    float acc[4][4][4];
#pragma unroll
    for (int mi = 0; mi < 4; ++mi)
#pragma unroll
        for (int ni = 0; ni < 4; ++ni)
#pragma unroll
            for (int r = 0; r < 4; ++r) acc[mi][ni][r] = 0.f;

    // prologue: tile 0 into buf 0
    LOAD_TILE(sA0, sB0, 0);

    const int NKT = DIM / 16;  // 128
    for (int kt = 0; kt < NKT; ++kt) {
        asm volatile("cp.async.wait_group 0;" ::: "memory");
        __syncthreads();

        const unsigned int aBase = (kt & 1) ? sA1 : sA0;
        const unsigned int bBase = (kt & 1) ? sB1 : sB0;

        if (kt + 1 < NKT) {
            const unsigned int aN = (kt & 1) ? sA0 : sA1;
            const unsigned int bN = (kt & 1) ? sB0 : sB1;
            LOAD_TILE(aN, bN, (kt + 1) * 16);
        }

#pragma unroll
        for (int kk = 0; kk < 16; kk += 8) {
            unsigned int af[4][4];
#pragma unroll
            for (int mi = 0; mi < 4; ++mi) {
                unsigned int addr = aBase + (offA[mi] + (unsigned)kk) * 4;
                asm volatile(
                    "ldmatrix.sync.aligned.m8n8.x4.shared.b16 {%0,%1,%2,%3}, [%4];"
                    : "=r"(af[mi][0]), "=r"(af[mi][1]), "=r"(af[mi][2]), "=r"(af[mi][3])
                    : "r"(addr));
            }
            unsigned int bf[4][2];
#pragma unroll
            for (int pr = 0; pr < 2; ++pr) {
                unsigned int addr = bBase + (offB[pr] + (unsigned)kk) * 4;
                asm volatile(
                    "ldmatrix.sync.aligned.m8n8.x4.shared.b16 {%0,%1,%2,%3}, [%4];"
                    : "=r"(bf[pr * 2][0]), "=r"(bf[pr * 2][1]),
                      "=r"(bf[pr * 2 + 1][0]), "=r"(bf[pr * 2 + 1][1])
                    : "r"(addr));
            }
#pragma unroll
            for (int mi = 0; mi < 4; ++mi)
#pragma unroll
                for (int ni = 0; ni < 4; ++ni) {
                    asm volatile(
                        "mma.sync.aligned.m16n8k8.row.col.f32.tf32.tf32.f32 "
                        "{%0,%1,%2,%3}, {%4,%5,%6,%7}, {%8,%9}, {%0,%1,%2,%3};"
                        : "+f"(acc[mi][ni][0]), "+f"(acc[mi][ni][1]),
                          "+f"(acc[mi][ni][2]), "+f"(acc[mi][ni][3])
                        : "r"(af[mi][0]), "r"(af[mi][1]), "r"(af[mi][2]), "r"(af[mi][3]),
                          "r"(bf[ni][0]), "r"(bf[ni][1]));
                }
        }
    }
#undef LOAD_TILE
#undef CPA

    // epilogue: feats = X + relu(Y)
    const float* Xb = X + (size_t)m0 * DIM + n0;
    float* Fb = g_feats + (size_t)m0 * DIM + n0;
#pragma unroll
    for (int mi = 0; mi < 4; ++mi) {
        int r  = wm + mi * 16 + (lane >> 2);
#pragma unroll
        for (int ni = 0; ni < 4; ++ni) {
            int cc = wn + ni * 8 + 2 * (lane & 3);
            {
                float2 xv = *(const float2*)(Xb + (size_t)r * DIM + cc);
                float2 o;
                o.x = xv.x + fmaxf(acc[mi][ni][0], 0.f);
                o.y = xv.y + fmaxf(acc[mi][ni][1], 0.f);
                *(float2*)(Fb + (size_t)r * DIM + cc) = o;
            }
            {
                int r2 = r + 8;
                float2 xv = *(const float2*)(Xb + (size_t)r2 * DIM + cc);
                float2 o;
                o.x = xv.x + fmaxf(acc[mi][ni][2], 0.f);
                o.y = xv.y + fmaxf(acc[mi][ni][3], 0.f);
                *(float2*)(Fb + (size_t)r2 * DIM + cc) = o;
            }
        }
    }
}

// ---------------------------------------------------------------------------
// kC1: p_e[c][p][o] = protos[c,p,:] . w2i[o,:]   (unchanged)
// ---------------------------------------------------------------------------
__global__ __launch_bounds__(256) void kC1(const float* __restrict__ protos,
                                           const float* __restrict__ w2i)
{
    const int c  = blockIdx.y;
    const int o0 = blockIdx.x * 32;
    __shared__ __align__(16) float prs[NPRO * DIM];

    const int tid = threadIdx.x;
    const int lane = tid & 31;
    const int w = tid >> 5;

    {
        const float4* src = (const float4*)(protos + (size_t)c * NPRO * DIM);
        float4* dst = (float4*)prs;
        for (int i = tid; i < NPRO * DIM / 4; i += 256) dst[i] = src[i];
    }
    __syncthreads();

#pragma unroll
    for (int oi = 0; oi < 4; ++oi) {
        int o = o0 + w * 4 + oi;
        float acc[NPRO] = {0.f, 0.f, 0.f, 0.f, 0.f};
        for (int d = lane; d < DIM; d += 32) {
            float wv = w2i[(size_t)o * DIM + d];
#pragma unroll
            for (int p = 0; p < NPRO; ++p) acc[p] += prs[p * DIM + d] * wv;
        }
#pragma unroll
        for (int p = 0; p < NPRO; ++p) {
#pragma unroll
            for (int off = 16; off > 0; off >>= 1)
                acc[p] += __shfl_xor_sync(0xffffffffu, acc[p], off);
        }
        if (lane == 0) {
#pragma unroll
            for (int p = 0; p < NPRO; ++p)
                g_pe[((size_t)c * NPRO + p) * OCH + o] = acc[p];
        }
    }
}

// ---------------------------------------------------------------------------
// kC2: q[c][p][d] = sum_o p_e[c][p][o] * w1i[o][d]   (unchanged)
// ---------------------------------------------------------------------------
__global__ __launch_bounds__(256) void kC2(const float* __restrict__ w1i)
{
    const int c  = blockIdx.y;
    const int d0 = blockIdx.x * 256;
    __shared__ __align__(16) float pes[NPRO * OCH];

    const int tid = threadIdx.x;
    {
        const float4* src = (const float4*)(g_pe + (size_t)c * NPRO * OCH);
        float4* dst = (float4*)pes;
        for (int i = tid; i < NPRO * OCH / 4; i += 256) dst[i] = src[i];
    }
    __syncthreads();

    const int d = d0 + tid;
    float acc[NPRO] = {0.f, 0.f, 0.f, 0.f, 0.f};
#pragma unroll 4
    for (int o = 0; o < OCH; ++o) {
        float wv = w1i[(size_t)o * DIM + d];
#pragma unroll
        for (int p = 0; p < NPRO; ++p) acc[p] += pes[p * OCH + o] * wv;
    }
#pragma unroll
    for (int p = 0; p < NPRO; ++p)
        g_q[((size_t)c * NPRO + p) * DIM + d] = acc[p];
}

// ---------------------------------------------------------------------------
// kC3: s[c][p][n] = (1/16) * feats[c,n,:] . q[c,p,:]   (unchanged)
// ---------------------------------------------------------------------------
__global__ __launch_bounds__(256) void kC3()
{
    const int c  = blockIdx.y;
    const int n0 = blockIdx.x * 32;
    __shared__ __align__(16) float qsm[NPRO * DIM];

    const int tid = threadIdx.x;
    const int lane = tid & 31;
    const int w = tid >> 5;
    const float* F = g_feats + (size_t)c * (NGRP * NSEQ) * DIM;

    {
        const float4* src = (const float4*)(g_q + (size_t)c * NPRO * DIM);
        float4* dst = (float4*)qsm;
        for (int i = tid; i < NPRO * DIM / 4; i += 256) dst[i] = src[i];
    }
    __syncthreads();

#pragma unroll
    for (int ni = 0; ni < 4; ++ni) {
        int n = n0 + w * 4 + ni;
        const float* fr = F + (size_t)n * DIM;
        float acc[NPRO] = {0.f, 0.f, 0.f, 0.f, 0.f};
        for (int d = lane; d < DIM; d += 32) {
            float fv = fr[d];
#pragma unroll
            for (int p = 0; p < NPRO; ++p) acc[p] += fv * qsm[p * DIM + d];
        }
#pragma unroll
        for (int p = 0; p < NPRO; ++p) {
#pragma unroll
            for (int off = 16; off > 0; off >>= 1)
                acc[p] += __shfl_xor_sync(0xffffffffu, acc[p], off);
        }
        if (lane == 0) {
#pragma unroll
            for (int p = 0; p < NPRO; ++p)
                g_s[((size_t)c * NPRO + p) * OCH + n] = acc[p] * 0.0625f;
        }
    }
}

// ---------------------------------------------------------------------------
// kC4: softmax + out = att2 @ feats   (unchanged)
// ---------------------------------------------------------------------------
__global__ __launch_bounds__(256) void kC4(float* __restrict__ outp)
{
    const int c  = blockIdx.y;
    const int d0 = blockIdx.x * 256;
    __shared__ __align__(16) float att[NPRO * OCH];

    const int tid = threadIdx.x;
    const int lane = tid & 31;
    const int w = tid >> 5;
    const float* F = g_feats + (size_t)c * (NGRP * NSEQ) * DIM;

    {
        const float4* src = (const float4*)(g_s + (size_t)c * NPRO * OCH);
        float4* dst = (float4*)att;
        for (int i = tid; i < NPRO * OCH / 4; i += 256) dst[i] = src[i];
    }
    __syncthreads();

    if (w < NPRO) {
        const int p = w;
        float mx = -1e30f;
        for (int n = lane; n < OCH; n += 32) mx = fmaxf(mx, att[p * OCH + n]);
#pragma unroll
        for (int off = 16; off > 0; off >>= 1)
            mx = fmaxf(mx, __shfl_xor_sync(0xffffffffu, mx, off));
        float sm = 0.f;
        for (int n = lane; n < OCH; n += 32) {
            float e = expf(att[p * OCH + n] - mx);
            att[p * OCH + n] = e;
            sm += e;
        }
#pragma unroll
        for (int off = 16; off > 0; off >>= 1)
            sm += __shfl_xor_sync(0xffffffffu, sm, off);
        float inv = 1.f / sm;
        for (int n = lane; n < OCH; n += 32) att[p * OCH + n] *= inv;
    }
    __syncthreads();

    const int d = d0 + tid;
    float acc[NPRO] = {0.f, 0.f, 0.f, 0.f, 0.f};
#pragma unroll 4
    for (int n = 0; n < OCH; ++n) {
        float fv = F[(size_t)n * DIM + d];
#pragma unroll
        for (int p = 0; p < NPRO; ++p) acc[p] += att[p * OCH + n] * fv;
    }
    float* ob = outp + (size_t)c * NPRO * DIM;
#pragma unroll
    for (int p = 0; p < NPRO; ++p) ob[(size_t)p * DIM + d] = acc[p];
}

// ---------------------------------------------------------------------------
extern "C" void kernel_launch(void* const* d_in, const int* in_sizes, int n_in,
                              void* d_out, int out_size)
{
    const float* topk   = (const float*)d_in[0];  // [64,8,32,2048]
    const float* protos = (const float*)d_in[1];  // [64,5,2048]
    const float* w1     = (const float*)d_in[2];  // [256,2048]
    const float* trans  = (const float*)d_in[3];  // [2048,2048]
    const float* w1i    = (const float*)d_in[4];  // [256,2048]
    const float* w2i    = (const float*)d_in[5];  // [256,2048]
    float* out = (float*)d_out;

    dim3 gA1(OCH / 128, MTOT / 128);  // (2, 128)
    kA1<<<gA1, 256>>>(topk, w1);
    kA2<<<NCLS * NGRP, 256>>>(topk);
    dim3 gB(DIM / 128, MTOT / 128);   // (16, 128)
    kB<<<gB, 256>>>(trans, topk);

    dim3 gC(8, NCLS);                 // (8, 64)
    kC1<<<gC, 256>>>(protos, w2i);
    kC2<<<gC, 256>>>(w1i);
    kC3<<<gC, 256>>>();
    kC4<<<gC, 256>>>(out);
}

// round 7
// speedup vs baseline: 3.2850x; 1.0432x over previous
#include <cuda_runtime.h>
#include <cstdint>

// Problem constants
#define NCLS 64
#define NGRP 8
#define NSEQ 32
#define DIM  2048
#define OCH  256
#define NPRO 5
#define MTOT (NCLS * NGRP * NSEQ)   // 16384

// Scratch (device globals; no runtime allocation allowed)
__device__ float g_ctx[(size_t)MTOT * DIM];    // 134 MB (tf32-rounded by kA2)
__device__ float g_feats[(size_t)MTOT * DIM];  // 134 MB
__device__ float g_e[(size_t)MTOT * OCH];      // 16.8 MB
__device__ float g_pe[(size_t)NCLS * NPRO * OCH];   // 327 KB
__device__ float g_q[(size_t)NCLS * NPRO * DIM];    // 2.6 MB
__device__ float g_s[(size_t)NCLS * NPRO * OCH];    // 327 KB
__device__ float g_trr[(size_t)DIM * DIM];     // 16.8 MB (tf32-rounded trans)
__device__ float g_w1r[(size_t)OCH * DIM];     // 2.1 MB  (tf32-rounded w1)

__device__ __forceinline__ float to_tf32(float x) {
    unsigned int t;
    asm("cvt.rna.tf32.f32 %0, %1;" : "=r"(t) : "f"(x));
    return __uint_as_float(t);
}

// ---------------------------------------------------------------------------
// kT: dst = tf32_rna(src), vectorized grid-stride. n % 4 == 0.
// ---------------------------------------------------------------------------
__global__ __launch_bounds__(256) void kT(const float* __restrict__ src,
                                          float* __restrict__ dst, int n4)
{
    int i = blockIdx.x * blockDim.x + threadIdx.x;
    int stride = gridDim.x * blockDim.x;
    for (; i < n4; i += stride) {
        float4 v = ((const float4*)src)[i];
        v.x = to_tf32(v.x); v.y = to_tf32(v.y);
        v.z = to_tf32(v.z); v.w = to_tf32(v.w);
        ((float4*)dst)[i] = v;
    }
}

// ===========================================================================
// Shared GEMM mainloop skeleton (cp.async + ldmatrix + 2-stage), 128x128 tile.
// ===========================================================================
#define KBS 20   // smem row stride in floats (80B, 16B-aligned, conflict-free)

// ---------------------------------------------------------------------------
// Kernel A1 v2: E = X @ w1r^T  (M=16384, N=256, K=2048)
// B operand pre-rounded (g_w1r); A operand (raw X) rounded in registers.
// ---------------------------------------------------------------------------
__global__ __launch_bounds__(256) void kA1(const float* __restrict__ Xin)
{
    __shared__ __align__(16) float As[2][128 * KBS];
    __shared__ __align__(16) float Bs[2][128 * KBS];

    const int tid  = threadIdx.x;
    const int lane = tid & 31;
    const int wid  = tid >> 5;
    const int wm   = (wid & 1) * 64;
    const int wn   = (wid >> 1) * 32;

    const int m0 = blockIdx.y * 128;
    const int n0 = blockIdx.x * 128;

    const float* Ab = Xin + (size_t)m0 * DIM;
    const float* Bb = g_w1r + (size_t)n0 * DIM;

    const int lrow0 = tid >> 2;
    const int lrow1 = (tid + 256) >> 2;
    const int lq    = (tid & 3) * 4;

    const unsigned int sA0 = (unsigned int)__cvta_generic_to_shared(&As[0][0]);
    const unsigned int sA1 = (unsigned int)__cvta_generic_to_shared(&As[1][0]);
    const unsigned int sB0 = (unsigned int)__cvta_generic_to_shared(&Bs[0][0]);
    const unsigned int sB1 = (unsigned int)__cvta_generic_to_shared(&Bs[1][0]);

#define CPA(dst_u32, srcp) \
    asm volatile("cp.async.cg.shared.global [%0], [%1], 16;" :: "r"(dst_u32), "l"(srcp) : "memory")

#define LOAD_TILE(bufA, bufB, k0_) do {                                              \
    CPA(bufA + (unsigned)(lrow0 * KBS + lq) * 4, Ab + (size_t)lrow0 * DIM + (k0_) + lq); \
    CPA(bufA + (unsigned)(lrow1 * KBS + lq) * 4, Ab + (size_t)lrow1 * DIM + (k0_) + lq); \
    CPA(bufB + (unsigned)(lrow0 * KBS + lq) * 4, Bb + (size_t)lrow0 * DIM + (k0_) + lq); \
    CPA(bufB + (unsigned)(lrow1 * KBS + lq) * 4, Bb + (size_t)lrow1 * DIM + (k0_) + lq); \
    asm volatile("cp.async.commit_group;" ::: "memory");                             \
} while (0)

    unsigned int offA[4];
#pragma unroll
    for (int mi = 0; mi < 4; ++mi)
        offA[mi] = (unsigned)((wm + mi * 16 + ((lane >> 3) & 1) * 8 + (lane & 7)) * KBS
                              + (lane >> 4) * 4);
    unsigned int offB[2];
#pragma unroll
    for (int pr = 0; pr < 2; ++pr)
        offB[pr] = (unsigned)((wn + pr * 16 + ((lane >> 4) & 1) * 8 + (lane & 7)) * KBS
                              + ((lane >> 3) & 1) * 4);

    float acc[4][4][4];
#pragma unroll
    for (int mi = 0; mi < 4; ++mi)
#pragma unroll
        for (int ni = 0; ni < 4; ++ni)
#pragma unroll
            for (int r = 0; r < 4; ++r) acc[mi][ni][r] = 0.f;

    LOAD_TILE(sA0, sB0, 0);

    const int NKT = DIM / 16;
    for (int kt = 0; kt < NKT; ++kt) {
        asm volatile("cp.async.wait_group 0;" ::: "memory");
        __syncthreads();

        const unsigned int aBase = (kt & 1) ? sA1 : sA0;
        const unsigned int bBase = (kt & 1) ? sB1 : sB0;

        if (kt + 1 < NKT) {
            const unsigned int aN = (kt & 1) ? sA0 : sA1;
            const unsigned int bN = (kt & 1) ? sB0 : sB1;
            LOAD_TILE(aN, bN, (kt + 1) * 16);
        }

#pragma unroll
        for (int kk = 0; kk < 16; kk += 8) {
            unsigned int af[4][4];
#pragma unroll
            for (int mi = 0; mi < 4; ++mi) {
                unsigned int addr = aBase + (offA[mi] + (unsigned)kk) * 4;
                asm volatile(
                    "ldmatrix.sync.aligned.m8n8.x4.shared.b16 {%0,%1,%2,%3}, [%4];"
                    : "=r"(af[mi][0]), "=r"(af[mi][1]), "=r"(af[mi][2]), "=r"(af[mi][3])
                    : "r"(addr));
                // round raw X fragments to tf32 (RNA) in registers
#pragma unroll
                for (int j = 0; j < 4; ++j)
                    af[mi][j] = __float_as_uint(to_tf32(__uint_as_float(af[mi][j])));
            }
            unsigned int bf[4][2];
#pragma unroll
            for (int pr = 0; pr < 2; ++pr) {
                unsigned int addr = bBase + (offB[pr] + (unsigned)kk) * 4;
                asm volatile(
                    "ldmatrix.sync.aligned.m8n8.x4.shared.b16 {%0,%1,%2,%3}, [%4];"
                    : "=r"(bf[pr * 2][0]), "=r"(bf[pr * 2][1]),
                      "=r"(bf[pr * 2 + 1][0]), "=r"(bf[pr * 2 + 1][1])
                    : "r"(addr));
            }
#pragma unroll
            for (int mi = 0; mi < 4; ++mi)
#pragma unroll
                for (int ni = 0; ni < 4; ++ni) {
                    asm volatile(
                        "mma.sync.aligned.m16n8k8.row.col.f32.tf32.tf32.f32 "
                        "{%0,%1,%2,%3}, {%4,%5,%6,%7}, {%8,%9}, {%0,%1,%2,%3};"
                        : "+f"(acc[mi][ni][0]), "+f"(acc[mi][ni][1]),
                          "+f"(acc[mi][ni][2]), "+f"(acc[mi][ni][3])
                        : "r"(af[mi][0]), "r"(af[mi][1]), "r"(af[mi][2]), "r"(af[mi][3]),
                          "r"(bf[ni][0]), "r"(bf[ni][1]));
                }
        }
    }
#undef LOAD_TILE
#undef CPA

    float* Eb = g_e + (size_t)m0 * OCH + n0;
#pragma unroll
    for (int mi = 0; mi < 4; ++mi) {
        int r = wm + mi * 16 + (lane >> 2);
#pragma unroll
        for (int ni = 0; ni < 4; ++ni) {
            int cc = wn + ni * 8 + 2 * (lane & 3);
            *(float2*)(Eb + (size_t)r * OCH + cc) = make_float2(acc[mi][ni][0], acc[mi][ni][1]);
            *(float2*)(Eb + (size_t)(r + 8) * OCH + cc) = make_float2(acc[mi][ni][2], acc[mi][ni][3]);
        }
    }
}

// ---------------------------------------------------------------------------
// Kernel A2: per (class, group): scores from E, softmax, ctx = att @ X.
// ctx stored tf32-RNA-rounded (consumed only by kB's A operand).
// ---------------------------------------------------------------------------
__global__ __launch_bounds__(256) void kA2(const float* __restrict__ Xall)
{
    const int blk = blockIdx.x;
    const float* X  = Xall + (size_t)blk * NSEQ * DIM;
    const float* E  = g_e + (size_t)blk * NSEQ * OCH;
    float* CTX      = g_ctx + (size_t)blk * NSEQ * DIM;

    __shared__ __align__(16) float Ws[32][260];
    __shared__ __align__(16) float Ss[32][32];

    const int tid = threadIdx.x;

#pragma unroll
    for (int r = 0; r < 8; ++r) {
        int idx = r * 256 + tid;
        int row = idx >> 6;
        int c4  = idx & 63;
        float4 v = *(const float4*)(E + (size_t)row * OCH + c4 * 4);
        *(float4*)&Ws[row][c4 * 4] = v;
    }
    __syncthreads();

    {
        int n = tid >> 3;
        int mbase = (tid & 7) * 4;
        float s0 = 0.f, s1 = 0.f, s2 = 0.f, s3 = 0.f;
        for (int o = 0; o < OCH; o += 4) {
            float4 a  = *(const float4*)&Ws[n][o];
            float4 b0 = *(const float4*)&Ws[mbase + 0][o];
            float4 b1 = *(const float4*)&Ws[mbase + 1][o];
            float4 b2 = *(const float4*)&Ws[mbase + 2][o];
            float4 b3 = *(const float4*)&Ws[mbase + 3][o];
            s0 += a.x * b0.x + a.y * b0.y + a.z * b0.z + a.w * b0.w;
            s1 += a.x * b1.x + a.y * b1.y + a.z * b1.z + a.w * b1.w;
            s2 += a.x * b2.x + a.y * b2.y + a.z * b2.z + a.w * b2.w;
            s3 += a.x * b3.x + a.y * b3.y + a.z * b3.z + a.w * b3.w;
        }
        Ss[n][mbase + 0] = s0 * 0.0625f;
        Ss[n][mbase + 1] = s1 * 0.0625f;
        Ss[n][mbase + 2] = s2 * 0.0625f;
        Ss[n][mbase + 3] = s3 * 0.0625f;
    }
    __syncthreads();

    {
        int w = tid >> 5, lane = tid & 31;
#pragma unroll
        for (int rr = 0; rr < 4; ++rr) {
            int n = w * 4 + rr;
            float v = Ss[n][lane];
            float mx = v;
#pragma unroll
            for (int off = 16; off > 0; off >>= 1)
                mx = fmaxf(mx, __shfl_xor_sync(0xffffffffu, mx, off));
            float ex = expf(v - mx);
            float sm = ex;
#pragma unroll
            for (int off = 16; off > 0; off >>= 1)
                sm += __shfl_xor_sync(0xffffffffu, sm, off);
            Ss[n][lane] = ex / sm;
        }
    }
    __syncthreads();

    float* Xc = &Ws[0][0];
    const int XCS = 68;
    const int txc = tid & 63;
    const int tyc = tid >> 6;

    for (int d0 = 0; d0 < DIM; d0 += 64) {
#pragma unroll
        for (int r = 0; r < 2; ++r) {
            int idx = r * 256 + tid;
            int row = idx >> 4, c4 = idx & 15;
            float4 v = *(const float4*)(X + (size_t)row * DIM + d0 + c4 * 4);
            *(float4*)&Xc[row * XCS + c4 * 4] = v;
        }
        __syncthreads();

        float outv[8];
#pragma unroll
        for (int i = 0; i < 8; ++i) outv[i] = 0.f;

#pragma unroll
        for (int m4 = 0; m4 < 32; m4 += 4) {
            float xv0 = Xc[(m4 + 0) * XCS + txc];
            float xv1 = Xc[(m4 + 1) * XCS + txc];
            float xv2 = Xc[(m4 + 2) * XCS + txc];
            float xv3 = Xc[(m4 + 3) * XCS + txc];
#pragma unroll
            for (int i = 0; i < 8; ++i) {
                float4 a = *(const float4*)&Ss[tyc * 8 + i][m4];
                outv[i] += a.x * xv0 + a.y * xv1 + a.z * xv2 + a.w * xv3;
            }
        }
#pragma unroll
        for (int i = 0; i < 8; ++i)
            CTX[(size_t)(tyc * 8 + i) * DIM + d0 + txc] = to_tf32(outv[i]);
        __syncthreads();
    }
}

// ---------------------------------------------------------------------------
// Kernel B v2: Y = ctx @ trr^T, feats = X + relu(Y).
// Both operands pre-rounded (g_ctx by kA2, g_trr by kT) -> no cvt in loop.
// ---------------------------------------------------------------------------
__global__ __launch_bounds__(256) void kB(const float* __restrict__ X)
{
    __shared__ __align__(16) float As[2][128 * KBS];
    __shared__ __align__(16) float Bs[2][128 * KBS];

    const int tid  = threadIdx.x;
    const int lane = tid & 31;
    const int wid  = tid >> 5;
    const int wm   = (wid & 1) * 64;
    const int wn   = (wid >> 1) * 32;

    const int m0 = blockIdx.y * 128;
    const int n0 = blockIdx.x * 128;

    const float* Ab = g_ctx + (size_t)m0 * DIM;
    const float* Bb = g_trr + (size_t)n0 * DIM;

    const int lrow0 = tid >> 2;
    const int lrow1 = (tid + 256) >> 2;
    const int lq    = (tid & 3) * 4;

    const unsigned int sA0 = (unsigned int)__cvta_generic_to_shared(&As[0][0]);
    const unsigned int sA1 = (unsigned int)__cvta_generic_to_shared(&As[1][0]);
    const unsigned int sB0 = (unsigned int)__cvta_generic_to_shared(&Bs[0][0]);
    const unsigned int sB1 = (unsigned int)__cvta_generic_to_shared(&Bs[1][0]);

#define CPA(dst_u32, srcp) \
    asm volatile("cp.async.cg.shared.global [%0], [%1], 16;" :: "r"(dst_u32), "l"(srcp) : "memory")

#define LOAD_TILE(bufA, bufB, k0_) do {                                              \
    CPA(bufA + (unsigned)(lrow0 * KBS + lq) * 4, Ab + (size_t)lrow0 * DIM + (k0_) + lq); \
    CPA(bufA + (unsigned)(lrow1 * KBS + lq) * 4, Ab + (size_t)lrow1 * DIM + (k0_) + lq); \
    CPA(bufB + (unsigned)(lrow0 * KBS + lq) * 4, Bb + (size_t)lrow0 * DIM + (k0_) + lq); \
    CPA(bufB + (unsigned)(lrow1 * KBS + lq) * 4, Bb + (size_t)lrow1 * DIM + (k0_) + lq); \
    asm volatile("cp.async.commit_group;" ::: "memory");                             \
} while (0)

    unsigned int offA[4];
#pragma unroll
    for (int mi = 0; mi < 4; ++mi)
        offA[mi] = (unsigned)((wm + mi * 16 + ((lane >> 3) & 1) * 8 + (lane & 7)) * KBS
                              + (lane >> 4) * 4);
    unsigned int offB[2];
#pragma unroll
    for (int pr = 0; pr < 2; ++pr)
        offB[pr] = (unsigned)((wn + pr * 16 + ((lane >> 4) & 1) * 8 + (lane & 7)) * KBS
                              + ((lane >> 3) & 1) * 4);

    float acc[4][4][4];
#pragma unroll
    for (int mi = 0; mi < 4; ++mi)
#pragma unroll
        for (int ni = 0; ni < 4; ++ni)
#pragma unroll
            for (int r = 0; r < 4; ++r) acc[mi][ni][r] = 0.f;

    LOAD_TILE(sA0, sB0, 0);

    const int NKT = DIM / 16;
    for (int kt = 0; kt < NKT; ++kt) {
        asm volatile("cp.async.wait_group 0;" ::: "memory");
        __syncthreads();

        const unsigned int aBase = (kt & 1) ? sA1 : sA0;
        const unsigned int bBase = (kt & 1) ? sB1 : sB0;

        if (kt + 1 < NKT) {
            const unsigned int aN = (kt & 1) ? sA0 : sA1;
            const unsigned int bN = (kt & 1) ? sB0 : sB1;
            LOAD_TILE(aN, bN, (kt + 1) * 16);
        }

#pragma unroll
        for (int kk = 0; kk < 16; kk += 8) {
            unsigned int af[4][4];
#pragma unroll
            for (int mi = 0; mi < 4; ++mi) {
                unsigned int addr = aBase + (offA[mi] + (unsigned)kk) * 4;
                asm volatile(
                    "ldmatrix.sync.aligned.m8n8.x4.shared.b16 {%0,%1,%2,%3}, [%4];"
                    : "=r"(af[mi][0]), "=r"(af[mi][1]), "=r"(af[mi][2]), "=r"(af[mi][3])
                    : "r"(addr));
            }
            unsigned int bf[4][2];
#pragma unroll
            for (int pr = 0; pr < 2; ++pr) {
                unsigned int addr = bBase + (offB[pr] + (unsigned)kk) * 4;
                asm volatile(
                    "ldmatrix.sync.aligned.m8n8.x4.shared.b16 {%0,%1,%2,%3}, [%4];"
                    : "=r"(bf[pr * 2][0]), "=r"(bf[pr * 2][1]),
                      "=r"(bf[pr * 2 + 1][0]), "=r"(bf[pr * 2 + 1][1])
                    : "r"(addr));
            }
#pragma unroll
            for (int mi = 0; mi < 4; ++mi)
#pragma unroll
                for (int ni = 0; ni < 4; ++ni) {
                    asm volatile(
                        "mma.sync.aligned.m16n8k8.row.col.f32.tf32.tf32.f32 "
                        "{%0,%1,%2,%3}, {%4,%5,%6,%7}, {%8,%9}, {%0,%1,%2,%3};"
                        : "+f"(acc[mi][ni][0]), "+f"(acc[mi][ni][1]),
                          "+f"(acc[mi][ni][2]), "+f"(acc[mi][ni][3])
                        : "r"(af[mi][0]), "r"(af[mi][1]), "r"(af[mi][2]), "r"(af[mi][3]),
                          "r"(bf[ni][0]), "r"(bf[ni][1]));
                }
        }
    }
#undef LOAD_TILE
#undef CPA

    const float* Xb = X + (size_t)m0 * DIM + n0;
    float* Fb = g_feats + (size_t)m0 * DIM + n0;
#pragma unroll
    for (int mi = 0; mi < 4; ++mi) {
        int r  = wm + mi * 16 + (lane >> 2);
#pragma unroll
        for (int ni = 0; ni < 4; ++ni) {
            int cc = wn + ni * 8 + 2 * (lane & 3);
            {
                float2 xv = *(const float2*)(Xb + (size_t)r * DIM + cc);
                float2 o;
                o.x = xv.x + fmaxf(acc[mi][ni][0], 0.f);
                o.y = xv.y + fmaxf(acc[mi][ni][1], 0.f);
                *(float2*)(Fb + (size_t)r * DIM + cc) = o;
            }
            {
                int r2 = r + 8;
                float2 xv = *(const float2*)(Xb + (size_t)r2 * DIM + cc);
                float2 o;
                o.x = xv.x + fmaxf(acc[mi][ni][2], 0.f);
                o.y = xv.y + fmaxf(acc[mi][ni][3], 0.f);
                *(float2*)(Fb + (size_t)r2 * DIM + cc) = o;
            }
        }
    }
}

// ---------------------------------------------------------------------------
// kC1..kC4 (unchanged)
// ---------------------------------------------------------------------------
__global__ __launch_bounds__(256) void kC1(const float* __restrict__ protos,
                                           const float* __restrict__ w2i)
{
    const int c  = blockIdx.y;
    const int o0 = blockIdx.x * 32;
    __shared__ __align__(16) float prs[NPRO * DIM];

    const int tid = threadIdx.x;
    const int lane = tid & 31;
    const int w = tid >> 5;

    {
        const float4* src = (const float4*)(protos + (size_t)c * NPRO * DIM);
        float4* dst = (float4*)prs;
        for (int i = tid; i < NPRO * DIM / 4; i += 256) dst[i] = src[i];
    }
    __syncthreads();

#pragma unroll
    for (int oi = 0; oi < 4; ++oi) {
        int o = o0 + w * 4 + oi;
        float acc[NPRO] = {0.f, 0.f, 0.f, 0.f, 0.f};
        for (int d = lane; d < DIM; d += 32) {
            float wv = w2i[(size_t)o * DIM + d];
#pragma unroll
            for (int p = 0; p < NPRO; ++p) acc[p] += prs[p * DIM + d] * wv;
        }
#pragma unroll
        for (int p = 0; p < NPRO; ++p) {
#pragma unroll
            for (int off = 16; off > 0; off >>= 1)
                acc[p] += __shfl_xor_sync(0xffffffffu, acc[p], off);
        }
        if (lane == 0) {
#pragma unroll
            for (int p = 0; p < NPRO; ++p)
                g_pe[((size_t)c * NPRO + p) * OCH + o] = acc[p];
        }
    }
}

__global__ __launch_bounds__(256) void kC2(const float* __restrict__ w1i)
{
    const int c  = blockIdx.y;
    const int d0 = blockIdx.x * 256;
    __shared__ __align__(16) float pes[NPRO * OCH];

    const int tid = threadIdx.x;
    {
        const float4* src = (const float4*)(g_pe + (size_t)c * NPRO * OCH);
        float4* dst = (float4*)pes;
        for (int i = tid; i < NPRO * OCH / 4; i += 256) dst[i] = src[i];
    }
    __syncthreads();

    const int d = d0 + tid;
    float acc[NPRO] = {0.f, 0.f, 0.f, 0.f, 0.f};
#pragma unroll 4
    for (int o = 0; o < OCH; ++o) {
        float wv = w1i[(size_t)o * DIM + d];
#pragma unroll
        for (int p = 0; p < NPRO; ++p) acc[p] += pes[p * OCH + o] * wv;
    }
#pragma unroll
    for (int p = 0; p < NPRO; ++p)
        g_q[((size_t)c * NPRO + p) * DIM + d] = acc[p];
}

__global__ __launch_bounds__(256) void kC3()
{
    const int c  = blockIdx.y;
    const int n0 = blockIdx.x * 32;
    __shared__ __align__(16) float qsm[NPRO * DIM];

    const int tid = threadIdx.x;
    const int lane = tid & 31;
    const int w = tid >> 5;
    const float* F = g_feats + (size_t)c * (NGRP * NSEQ) * DIM;

    {
        const float4* src = (const float4*)(g_q + (size_t)c * NPRO * DIM);
        float4* dst = (float4*)qsm;
        for (int i = tid; i < NPRO * DIM / 4; i += 256) dst[i] = src[i];
    }
    __syncthreads();

#pragma unroll
    for (int ni = 0; ni < 4; ++ni) {
        int n = n0 + w * 4 + ni;
        const float* fr = F + (size_t)n * DIM;
        float acc[NPRO] = {0.f, 0.f, 0.f, 0.f, 0.f};
        for (int d = lane; d < DIM; d += 32) {
            float fv = fr[d];
#pragma unroll
            for (int p = 0; p < NPRO; ++p) acc[p] += fv * qsm[p * DIM + d];
        }
#pragma unroll
        for (int p = 0; p < NPRO; ++p) {
#pragma unroll
            for (int off = 16; off > 0; off >>= 1)
                acc[p] += __shfl_xor_sync(0xffffffffu, acc[p], off);
        }
        if (lane == 0) {
#pragma unroll
            for (int p = 0; p < NPRO; ++p)
                g_s[((size_t)c * NPRO + p) * OCH + n] = acc[p] * 0.0625f;
        }
    }
}

__global__ __launch_bounds__(256) void kC4(float* __restrict__ outp)
{
    const int c  = blockIdx.y;
    const int d0 = blockIdx.x * 256;
    __shared__ __align__(16) float att[NPRO * OCH];

    const int tid = threadIdx.x;
    const int lane = tid & 31;
    const int w = tid >> 5;
    const float* F = g_feats + (size_t)c * (NGRP * NSEQ) * DIM;

    {
        const float4* src = (const float4*)(g_s + (size_t)c * NPRO * OCH);
        float4* dst = (float4*)att;
        for (int i = tid; i < NPRO * OCH / 4; i += 256) dst[i] = src[i];
    }
    __syncthreads();

    if (w < NPRO) {
        const int p = w;
        float mx = -1e30f;
        for (int n = lane; n < OCH; n += 32) mx = fmaxf(mx, att[p * OCH + n]);
#pragma unroll
        for (int off = 16; off > 0; off >>= 1)
            mx = fmaxf(mx, __shfl_xor_sync(0xffffffffu, mx, off));
        float sm = 0.f;
        for (int n = lane; n < OCH; n += 32) {
            float e = expf(att[p * OCH + n] - mx);
            att[p * OCH + n] = e;
            sm += e;
        }
#pragma unroll
        for (int off = 16; off > 0; off >>= 1)
            sm += __shfl_xor_sync(0xffffffffu, sm, off);
        float inv = 1.f / sm;
        for (int n = lane; n < OCH; n += 32) att[p * OCH + n] *= inv;
    }
    __syncthreads();

    const int d = d0 + tid;
    float acc[NPRO] = {0.f, 0.f, 0.f, 0.f, 0.f};
#pragma unroll 4
    for (int n = 0; n < OCH; ++n) {
        float fv = F[(size_t)n * DIM + d];
#pragma unroll
        for (int p = 0; p < NPRO; ++p) acc[p] += att[p * OCH + n] * fv;
    }
    float* ob = outp + (size_t)c * NPRO * DIM;
#pragma unroll
    for (int p = 0; p < NPRO; ++p) ob[(size_t)p * DIM + d] = acc[p];
}

// ---------------------------------------------------------------------------
extern "C" void kernel_launch(void* const* d_in, const int* in_sizes, int n_in,
                              void* d_out, int out_size)
{
    const float* topk   = (const float*)d_in[0];  // [64,8,32,2048]
    const float* protos = (const float*)d_in[1];  // [64,5,2048]
    const float* w1     = (const float*)d_in[2];  // [256,2048]
    const float* trans  = (const float*)d_in[3];  // [2048,2048]
    const float* w1i    = (const float*)d_in[4];  // [256,2048]
    const float* w2i    = (const float*)d_in[5];  // [256,2048]
    float* out = (float*)d_out;

    // pre-round weights to tf32 (RNA)
    float* trr = nullptr; cudaGetSymbolAddress((void**)&trr, g_trr);
    float* w1r = nullptr; cudaGetSymbolAddress((void**)&w1r, g_w1r);
    kT<<<1024, 256>>>(trans, trr, DIM * DIM / 4);
    kT<<<64, 256>>>(w1, w1r, OCH * DIM / 4);

    dim3 gA1(OCH / 128, MTOT / 128);  // (2, 128)
    kA1<<<gA1, 256>>>(topk);
    kA2<<<NCLS * NGRP, 256>>>(topk);
    dim3 gB(DIM / 128, MTOT / 128);   // (16, 128)
    kB<<<gB, 256>>>(topk);

    dim3 gC(8, NCLS);                 // (8, 64)
    kC1<<<gC, 256>>>(protos, w2i);
    kC2<<<gC, 256>>>(w1i);
    kC3<<<gC, 256>>>();
    kC4<<<gC, 256>>>(out);
}